// round 9
// baseline (speedup 1.0000x reference)
#include <cuda_runtime.h>
#include <cuda_bf16.h>
#include <math.h>
#include <cstdint>

#define BB   256      // batch
#define TT   512      // time steps
#define IDIM 128      // input dim
#define HH   256      // hidden dim
#define CDIM 1000     // classes
#define G4   (4*HH)   // 1024 gate columns

// ---------------- scratch (static device allocations; no cudaMalloc) ----------------
// g_xp layout: [t][b][jp][g][2]
__device__ float g_xp[(size_t)BB * TT * G4];
__device__ float g_h[2][BB * HH];              // fp32 hidden (only needed for fc)
__device__ __nv_bfloat16 g_hsp_hi[2][BB * HH]; // split hidden state, double buffered
__device__ __nv_bfloat16 g_hsp_lo[2][BB * HH];
__device__ unsigned g_stamp[8 * 32];           // per (group, jslice) step stamps

// bf16 split buffers for tensor-core projections
__device__ __nv_bfloat16 g_a_hi[(size_t)BB * TT * HH];
__device__ __nv_bfloat16 g_a_lo[(size_t)BB * TT * HH];
__device__ __nv_bfloat16 g_w_hi[(size_t)G4 * HH];
__device__ __nv_bfloat16 g_w_lo[(size_t)G4 * HH];

// ---------------- generic helpers ----------------
__device__ __forceinline__ float sigmoidf_(float x) {
    return 1.0f / (1.0f + __expf(-x));
}
__device__ __forceinline__ float tanhf_(float x) {
    float ax = fabsf(x);
    float e  = __expf(-2.0f * ax);
    float r  = (1.0f - e) / (1.0f + e);
    return copysignf(r, x);
}
__device__ __forceinline__ uint32_t smem_u32_(const void* p) {
    uint32_t a;
    asm("{ .reg .u64 t; cvta.to.shared.u64 t, %1; cvt.u32.u64 %0, t; }"
        : "=r"(a) : "l"(p));
    return a;
}
static __device__ __forceinline__ uint32_t sw128(uint32_t off) {
    return off ^ ((off >> 3) & 0x70);
}
__device__ __forceinline__ unsigned pack_hi_(float x, float y) {
    return (unsigned)__bfloat16_as_ushort(__float2bfloat16(x))
         | ((unsigned)__bfloat16_as_ushort(__float2bfloat16(y)) << 16);
}
__device__ __forceinline__ unsigned pack_lo_(float x, float y) {
    float rx = x - __bfloat162float(__float2bfloat16(x));
    float ry = y - __bfloat162float(__float2bfloat16(y));
    return pack_hi_(rx, ry);
}

// cp.async (sm_80+; base-target safe)
__device__ __forceinline__ void cp16_(void* smem_dst, const void* gsrc) {
    uint32_t d = smem_u32_(smem_dst);
    asm volatile("cp.async.cg.shared.global [%0], [%1], 16;" :: "r"(d), "l"(gsrc));
}
#define CP_COMMIT() asm volatile("cp.async.commit_group;" ::: "memory")
#define CP_WAIT1()  asm volatile("cp.async.wait_group 1;" ::: "memory")
#define CP_WAIT0()  asm volatile("cp.async.wait_group 0;" ::: "memory")

// ldmatrix x4 (sm_75+)
#define LDMATRIX_X4(r0, r1, r2, r3, addr) \
    asm volatile("ldmatrix.sync.aligned.m8n8.x4.shared.b16 {%0,%1,%2,%3}, [%4];" \
                 : "=r"(r0), "=r"(r1), "=r"(r2), "=r"(r3) : "r"(addr))

// mma m16n8k16 bf16 (sm_80+)
#define MMA_BF16(d, a, b0v, b1v) \
    asm volatile("mma.sync.aligned.m16n8k16.row.col.f32.bf16.bf16.f32 " \
                 "{%0,%1,%2,%3}, {%4,%5,%6,%7}, {%8,%9}, {%0,%1,%2,%3};" \
                 : "+f"((d)[0]), "+f"((d)[1]), "+f"((d)[2]), "+f"((d)[3]) \
                 : "r"((a)[0]), "r"((a)[1]), "r"((a)[2]), "r"((a)[3]), \
                   "r"(b0v), "r"(b1v))

// ---------------- bf16 split conversion (x, Wih0, Wih1 only) ----------------
__global__ __launch_bounds__(256) void split_bf16_kernel(
    const float* __restrict__ src, int to_w, size_t n4)
{
    size_t i = (size_t)blockIdx.x * blockDim.x + threadIdx.x;
    if (i >= n4) return;
    const float4* s = (const float4*)src;
    __nv_bfloat162* dh = (__nv_bfloat162*)(to_w ? g_w_hi : g_a_hi);
    __nv_bfloat162* dl = (__nv_bfloat162*)(to_w ? g_w_lo : g_a_lo);
    float4 v = s[i];
    __nv_bfloat16 h0 = __float2bfloat16(v.x);
    __nv_bfloat16 h1 = __float2bfloat16(v.y);
    __nv_bfloat16 h2 = __float2bfloat16(v.z);
    __nv_bfloat16 h3 = __float2bfloat16(v.w);
    __nv_bfloat16 l0 = __float2bfloat16(v.x - __bfloat162float(h0));
    __nv_bfloat16 l1 = __float2bfloat16(v.y - __bfloat162float(h1));
    __nv_bfloat16 l2 = __float2bfloat16(v.z - __bfloat162float(h2));
    __nv_bfloat16 l3 = __float2bfloat16(v.w - __bfloat162float(h3));
    dh[i * 2 + 0] = __halves2bfloat162(h0, h1);
    dh[i * 2 + 1] = __halves2bfloat162(h2, h3);
    dl[i * 2 + 0] = __halves2bfloat162(l0, l1);
    dl[i * 2 + 1] = __halves2bfloat162(l2, l3);
}

// ---------------- HMMA projection (unchanged from passing R8) ----------------
#define PSTG 16384
#define PROJ_SMEM_TOTAL (4 * PSTG + 512)

__global__ __launch_bounds__(256) void proj_mma_kernel(
    const float* __restrict__ b1, const float* __restrict__ b2, int K)
{
    extern __shared__ char smem[];
    float* bias_s = (float*)(smem + 4 * PSTG);

    const int tid  = threadIdx.x;
    const int lane = tid & 31;
    const int w    = tid >> 5;
    const int wm   = w & 3;
    const int wn   = w >> 2;
    const int n0   = blockIdx.x * 128;
    const int m0   = blockIdx.y * 128;

    if (tid < 128) bias_s[tid] = b1[n0 + tid] + b2[n0 + tid];

    const int kchunks = K >> 6;
    const int C = 3 * kchunks;

    auto prefetch = [&](int c, int stage) {
        const int s  = c / kchunks;
        const int kc = c % kchunks;
        const __nv_bfloat16* a_src = (s == 2) ? g_a_lo : g_a_hi;
        const __nv_bfloat16* w_src = (s == 1) ? g_w_lo : g_w_hi;
        char* abuf = smem + stage * 2 * PSTG;
        char* bbuf = abuf + PSTG;
#pragma unroll
        for (int i = 0; i < 4; i++) {
            int id  = tid + i * 256;
            int row = id >> 3;
            int ch  = id & 7;
            cp16_(abuf + sw128((uint32_t)(row * 128 + ch * 16)),
                  a_src + (size_t)(m0 + row) * K + kc * 64 + ch * 8);
            cp16_(bbuf + sw128((uint32_t)(row * 128 + ch * 16)),
                  w_src + (size_t)(n0 + row) * K + kc * 64 + ch * 8);
        }
    };

    float acc[2][8][4];
#pragma unroll
    for (int mf = 0; mf < 2; mf++)
#pragma unroll
        for (int nf = 0; nf < 8; nf++)
#pragma unroll
            for (int q = 0; q < 4; q++) acc[mf][nf][q] = 0.0f;

    prefetch(0, 0);
    CP_COMMIT();

    const int lrow = lane & 15;
    const int lch  = (lane >> 4) * 16;

    for (int c = 0; c < C; c++) {
        if (c + 1 < C) { prefetch(c + 1, (c + 1) & 1); CP_COMMIT(); CP_WAIT1(); }
        else           { CP_WAIT0(); }
        __syncthreads();

        char* abuf = smem + (c & 1) * 2 * PSTG;
        char* bbuf = abuf + PSTG;
        const uint32_t abase = smem_u32_(abuf);
        const uint32_t bbase = smem_u32_(bbuf);

#pragma unroll
        for (int k16 = 0; k16 < 4; k16++) {
            uint32_t afr[2][4];
#pragma unroll
            for (int mf = 0; mf < 2; mf++) {
                uint32_t addr = abase +
                    sw128((uint32_t)((wm * 32 + mf * 16 + lrow) * 128 + k16 * 32 + lch));
                LDMATRIX_X4(afr[mf][0], afr[mf][1], afr[mf][2], afr[mf][3], addr);
            }
#pragma unroll
            for (int nf2 = 0; nf2 < 4; nf2++) {
                uint32_t bm0, bm1, bm2, bm3;
                uint32_t addr = bbase +
                    sw128((uint32_t)((wn * 64 + nf2 * 16 + lrow) * 128 + k16 * 32 + lch));
                LDMATRIX_X4(bm0, bm1, bm2, bm3, addr);
#pragma unroll
                for (int mf = 0; mf < 2; mf++) {
                    MMA_BF16(acc[mf][2 * nf2 + 0], afr[mf], bm0, bm2);
                    MMA_BF16(acc[mf][2 * nf2 + 1], afr[mf], bm1, bm3);
                }
            }
        }
        __syncthreads();
    }

    const int rrow = lane >> 2;
    const int cq   = (lane & 3) * 2;
#pragma unroll
    for (int mf = 0; mf < 2; mf++) {
#pragma unroll
        for (int rr = 0; rr < 2; rr++) {
            int m = m0 + wm * 32 + mf * 16 + rrow + rr * 8;
            int t = m & (TT - 1);
            int b = m >> 9;
            float* obase = g_xp + ((size_t)t * BB + b) * G4;
#pragma unroll
            for (int nf = 0; nf < 8; nf++) {
                int nl = wn * 64 + nf * 8 + cq;
                int n  = n0 + nl;
                int g  = n >> 8;
                int jj = n & 255;
                float bv0 = bias_s[nl], bv1 = bias_s[nl + 1];
                float2 v = { acc[mf][nf][2 * rr + 0] + bv0,
                             acc[mf][nf][2 * rr + 1] + bv1 };
                *(float2*)(obase + (jj >> 1) * 8 + g * 2) = v;
            }
        }
    }
}

// ---------------- persistent LSTM layer kernel (HMMA, stamp sync) ----------------
// Grid (8, 8): blockIdx.x = batch group of 32, blockIdx.y = j slice of 32.
// Warp = one n16 slice of the 128 gate-cols (col c = g*32 + jl); full K=256.
#define WPLANE (128 * 576)                   // 73728
#define HPLANE (32 * 576)                    // 18432
#define GB_OFF (2 * WPLANE + 2 * HPLANE)     // 184320
#define PERSIST_SMEM_BYTES (GB_OFF + 32 * 128 * 4)   // 200704

__global__ __launch_bounds__(256, 1) void lstm_persist_kernel(
    const float* __restrict__ Whh, int write_a)
{
    extern __shared__ char smem[];
    char* w_hi = smem;
    char* w_lo = smem + WPLANE;
    char* h_hi = smem + 2 * WPLANE;
    char* h_lo = smem + 2 * WPLANE + HPLANE;
    float* gb  = (float*)(smem + GB_OFF);    // [32][128]

    const int tid  = threadIdx.x;
    const int lane = tid & 31;
    const int ns   = tid >> 5;       // warp = n16 slice 0..7
    const int grp  = blockIdx.x;
    const int jy   = blockIdx.y;
    const int b0   = grp * 32;
    const int j0   = jy * 32;
    const int jg   = tid & 15;       // j pair within slice
    const int bl   = tid >> 4;       // local batch 0..15 (handles bl and bl+16)
    const int j    = j0 + 2 * jg;
    const int jp   = (j0 >> 1) + jg;

    // ---- load + split Whh slice: plane row c = g*32+jl -> Whh[g*HH + j0 + jl]
    for (int i = tid; i < 128 * 64; i += 256) {
        int row = i >> 6, kq = i & 63;
        const float4 v = *(const float4*)(
            Whh + (size_t)((row >> 5) * HH + j0 + (row & 31)) * HH + kq * 4);
        uint2 hi = { pack_hi_(v.x, v.y), pack_hi_(v.z, v.w) };
        uint2 lo = { pack_lo_(v.x, v.y), pack_lo_(v.z, v.w) };
        uint32_t off = sw128((uint32_t)(row * 576 + kq * 8));
        *(uint2*)(w_hi + off) = hi;
        *(uint2*)(w_lo + off) = lo;
    }
    __syncthreads();

    const uint32_t whi_b = smem_u32_(w_hi);
    const uint32_t wlo_b = smem_u32_(w_lo);
    const uint32_t hhi_b = smem_u32_(h_hi);
    const uint32_t hlo_b = smem_u32_(h_lo);
    const int lrow = lane & 15;
    const int lch  = (lane >> 4) * 16;

    // launch-local stamp base (own slot; uniform across the group after any launch)
    const unsigned base = *(volatile unsigned*)&g_stamp[grp * 32 + jy];

    float cA0 = 0.0f, cA1 = 0.0f, cB0 = 0.0f, cB1 = 0.0f;

    for (int t = 0; t < TT; t++) {
        const int par = t & 1;

        // xp loads (independent of stamps; issue early)
        const float* xpA = g_xp + ((size_t)t * BB + b0 + bl) * G4 + (size_t)jp * 8;
        const float* xpB = g_xp + ((size_t)t * BB + b0 + bl + 16) * G4 + (size_t)jp * 8;
        float4 xa0 = *(const float4*)(xpA);
        float4 xa1 = *(const float4*)(xpA + 4);
        float4 xb0 = *(const float4*)(xpB);
        float4 xb1 = *(const float4*)(xpB + 4);

        if (t > 0) {
            // ---- stamp poll: thread s<8 spins on group slot s until >= base+t
            if (tid < 8) {
                const volatile unsigned* st = &g_stamp[grp * 32 + tid];
                unsigned need = base + (unsigned)t;
                while ((int)(*st - need) < 0) { }
            }
            __syncthreads();

            // ---- stage h_{t-1} split planes via cp.async (producer pre-split)
            const __nv_bfloat16* shi = g_hsp_hi[par];
            const __nv_bfloat16* slo = g_hsp_lo[par];
            for (int i = tid; i < 2048; i += 256) {
                int pl  = i >> 10;
                int rem = i & 1023;
                int row = rem >> 5;
                int kq  = rem & 31;
                const __nv_bfloat16* src =
                    (pl ? slo : shi) + (size_t)(b0 + row) * HH + kq * 8;
                char* dst = (pl ? h_lo : h_hi) + sw128((uint32_t)(row * 576 + kq * 16));
                cp16_(dst, src);
            }
            CP_COMMIT();
            CP_WAIT0();
            __syncthreads();

            // ---- HMMA: warp ns, M=32 (2 m16), N=16 (2 n8), K=256, 3 Dekker terms
            float acc[2][2][4];
#pragma unroll
            for (int mf = 0; mf < 2; mf++)
#pragma unroll
                for (int nf = 0; nf < 2; nf++)
#pragma unroll
                    for (int q = 0; q < 4; q++) acc[mf][nf][q] = 0.0f;

#pragma unroll
            for (int k16 = 0; k16 < 16; k16++) {
                const uint32_t kb = (uint32_t)(k16 * 32 + lch);
                uint32_t ahi[2][4], alo[2][4];
#pragma unroll
                for (int mf = 0; mf < 2; mf++) {
                    uint32_t roff = sw128((uint32_t)((mf * 16 + lrow) * 576) + kb);
                    LDMATRIX_X4(ahi[mf][0], ahi[mf][1], ahi[mf][2], ahi[mf][3],
                                hhi_b + roff);
                    LDMATRIX_X4(alo[mf][0], alo[mf][1], alo[mf][2], alo[mf][3],
                                hlo_b + roff);
                }
                uint32_t woff = sw128((uint32_t)((ns * 16 + lrow) * 576) + kb);
                uint32_t bh0, bh1, bh2, bh3, bl0, bl1, bl2, bl3;
                LDMATRIX_X4(bh0, bh1, bh2, bh3, whi_b + woff);
                LDMATRIX_X4(bl0, bl1, bl2, bl3, wlo_b + woff);
#pragma unroll
                for (int mf = 0; mf < 2; mf++) {
                    MMA_BF16(acc[mf][0], ahi[mf], bh0, bh2);
                    MMA_BF16(acc[mf][1], ahi[mf], bh1, bh3);
                    MMA_BF16(acc[mf][0], ahi[mf], bl0, bl2);
                    MMA_BF16(acc[mf][1], ahi[mf], bl1, bl3);
                    MMA_BF16(acc[mf][0], alo[mf], bh0, bh2);
                    MMA_BF16(acc[mf][1], alo[mf], bh1, bh3);
                }
            }

            // ---- dump gates to SMEM
            {
                const int rrow = lane >> 2;
                const int cq   = (lane & 3) * 2;
#pragma unroll
                for (int mf = 0; mf < 2; mf++) {
#pragma unroll
                    for (int nf = 0; nf < 2; nf++) {
                        int col = ns * 16 + nf * 8 + cq;
                        *(float2*)&gb[(mf * 16 + rrow) * 128 + col] =
                            make_float2(acc[mf][nf][0], acc[mf][nf][1]);
                        *(float2*)&gb[(mf * 16 + rrow + 8) * 128 + col] =
                            make_float2(acc[mf][nf][2], acc[mf][nf][3]);
                    }
                }
            }
            __syncthreads();
        }

        // ---- elementwise: 2 batches (bl, bl+16) x 2 j
        float* __restrict__ hnext = g_h[par ^ 1];
        __nv_bfloat16* __restrict__ dhi = g_hsp_hi[par ^ 1];
        __nv_bfloat16* __restrict__ dlo = g_hsp_lo[par ^ 1];
        float4 xs[2][2] = { {xa0, xa1}, {xb0, xb1} };
#pragma unroll
        for (int bb = 0; bb < 2; bb++) {
            int blr = bl + bb * 16;
            int b   = b0 + blr;
            float xg[4][2] = { {xs[bb][0].x, xs[bb][0].y}, {xs[bb][0].z, xs[bb][0].w},
                               {xs[bb][1].x, xs[bb][1].y}, {xs[bb][1].z, xs[bb][1].w} };
            float2 gate[4];
#pragma unroll
            for (int g = 0; g < 4; g++) {
                float gx = 0.0f, gy = 0.0f;
                if (t > 0) {
                    float2 p = *(float2*)&gb[blr * 128 + g * 32 + 2 * jg];
                    gx = p.x; gy = p.y;
                }
                gate[g].x = gx + xg[g][0];
                gate[g].y = gy + xg[g][1];
            }
            float i0 = sigmoidf_(gate[0].x), i1 = sigmoidf_(gate[0].y);
            float f0 = sigmoidf_(gate[1].x), f1 = sigmoidf_(gate[1].y);
            float g0 = tanhf_   (gate[2].x), g1 = tanhf_   (gate[2].y);
            float o0 = sigmoidf_(gate[3].x), o1 = sigmoidf_(gate[3].y);
            float& c0 = bb ? cB0 : cA0;
            float& c1 = bb ? cB1 : cA1;
            c0 = f0 * c0 + i0 * g0;
            c1 = f1 * c1 + i1 * g1;
            float2 hv = { o0 * tanhf_(c0), o1 * tanhf_(c1) };
            __stcg((float2*)(hnext + (size_t)b * HH + j), hv);
            unsigned uhi = pack_hi_(hv.x, hv.y);
            unsigned ulo = pack_lo_(hv.x, hv.y);
            __stcg((unsigned*)(dhi + (size_t)b * HH + j), uhi);
            __stcg((unsigned*)(dlo + (size_t)b * HH + j), ulo);
            if (write_a) {
                *(unsigned*)(g_a_hi + ((size_t)b * TT + t) * HH + j) = uhi;
                *(unsigned*)(g_a_lo + ((size_t)b * TT + t) * HH + j) = ulo;
            }
        }

        // ---- publish stamp (h writes globally visible first)
        __threadfence();
        __syncthreads();
        if (tid == 0)
            *(volatile unsigned*)&g_stamp[grp * 32 + jy] = base + (unsigned)t + 1u;
    }
}

// ---------------- final classifier ----------------
__global__ __launch_bounds__(256) void fc_kernel(
    const float* __restrict__ fcW, const float* __restrict__ fcb,
    float* __restrict__ out)
{
    __shared__ float hrow[HH];
    const int b = blockIdx.x;
    const float* __restrict__ h = g_h[0];   // final h (t=511 writes buffer 0)
    for (int k = threadIdx.x; k < HH; k += 256) hrow[k] = h[b * HH + k];
    __syncthreads();

    for (int c = threadIdx.x; c < CDIM; c += 256) {
        const float* __restrict__ w = fcW + (size_t)c * HH;
        float s = fcb[c];
#pragma unroll
        for (int k = 0; k < HH; k += 4) {
            float4 wv = *(const float4*)(w + k);
            s += hrow[k + 0] * wv.x;
            s += hrow[k + 1] * wv.y;
            s += hrow[k + 2] * wv.z;
            s += hrow[k + 3] * wv.w;
        }
        out[(size_t)b * CDIM + c] = s;
    }
}

// ---------------- launch ----------------
extern "C" void kernel_launch(void* const* d_in, const int* in_sizes, int n_in,
                              void* d_out, int out_size)
{
    const float* x    = (const float*)d_in[0];
    const float* Wih0 = (const float*)d_in[1];
    const float* Whh0 = (const float*)d_in[2];
    const float* bih0 = (const float*)d_in[3];
    const float* bhh0 = (const float*)d_in[4];
    const float* Wih1 = (const float*)d_in[5];
    const float* Whh1 = (const float*)d_in[6];
    const float* bih1 = (const float*)d_in[7];
    const float* bhh1 = (const float*)d_in[8];
    const float* fcW  = (const float*)d_in[9];
    const float* fcb  = (const float*)d_in[10];
    float* out = (float*)d_out;

    cudaFuncSetAttribute(lstm_persist_kernel,
                         cudaFuncAttributeMaxDynamicSharedMemorySize,
                         PERSIST_SMEM_BYTES);
    cudaFuncSetAttribute(proj_mma_kernel,
                         cudaFuncAttributeMaxDynamicSharedMemorySize,
                         PROJ_SMEM_TOTAL);

    const dim3 proj_grid(G4 / 128, (BB * TT) / 128);  // (8, 1024)
    const dim3 pers_grid(8, 8);                       // 64 CTAs

    // ---- layer 0 ----
    {
        size_t n4x = (size_t)BB * TT * IDIM / 4;
        size_t n4w = (size_t)G4 * IDIM / 4;
        split_bf16_kernel<<<(unsigned)((n4x + 255) / 256), 256>>>(x, 0, n4x);
        split_bf16_kernel<<<(unsigned)((n4w + 255) / 256), 256>>>(Wih0, 1, n4w);
        proj_mma_kernel<<<proj_grid, 256, PROJ_SMEM_TOTAL>>>(bih0, bhh0, IDIM);
        lstm_persist_kernel<<<pers_grid, 256, PERSIST_SMEM_BYTES>>>(Whh0, 1);
    }

    // ---- layer 1 (A split written by layer-0 recurrence; only W needs split) ----
    {
        size_t n4w = (size_t)G4 * HH / 4;
        split_bf16_kernel<<<(unsigned)((n4w + 255) / 256), 256>>>(Wih1, 1, n4w);
        proj_mma_kernel<<<proj_grid, 256, PROJ_SMEM_TOTAL>>>(bih1, bhh1, HH);
        lstm_persist_kernel<<<pers_grid, 256, PERSIST_SMEM_BYTES>>>(Whh1, 0);
    }

    // ---- classifier ----
    fc_kernel<<<BB, 256>>>(fcW, fcb, out);
}

// round 10
// speedup vs baseline: 1.2419x; 1.2419x over previous
#include <cuda_runtime.h>
#include <cuda_bf16.h>
#include <math.h>
#include <cstdint>

#define BB   256      // batch
#define TT   512      // time steps
#define IDIM 128      // input dim
#define HH   256      // hidden dim
#define CDIM 1000     // classes
#define G4   (4*HH)   // 1024 gate columns

// ---------------- scratch (static device allocations; no cudaMalloc) ----------------
// g_xp layout: [t][b][jp][g][2]
__device__ float g_xp[(size_t)BB * TT * G4];
__device__ float g_h[2][BB * HH];              // fp32 hidden (fc needs final)
__device__ __nv_bfloat16 g_hsp_hi[2][BB * HH]; // split hidden, double buffered
__device__ __nv_bfloat16 g_hsp_lo[2][BB * HH];
__device__ unsigned g_stamp[8 * 32];           // per (group, jslice) step stamps

// bf16 split buffers for tensor-core projections
__device__ __nv_bfloat16 g_a_hi[(size_t)BB * TT * HH];
__device__ __nv_bfloat16 g_a_lo[(size_t)BB * TT * HH];
__device__ __nv_bfloat16 g_w_hi[(size_t)G4 * HH];
__device__ __nv_bfloat16 g_w_lo[(size_t)G4 * HH];

// ---------------- generic helpers ----------------
__device__ __forceinline__ float sigmoidf_(float x) {
    return 1.0f / (1.0f + __expf(-x));
}
__device__ __forceinline__ float tanhf_(float x) {
    float ax = fabsf(x);
    float e  = __expf(-2.0f * ax);
    float r  = (1.0f - e) / (1.0f + e);
    return copysignf(r, x);
}
__device__ __forceinline__ uint32_t smem_u32_(const void* p) {
    uint32_t a;
    asm("{ .reg .u64 t; cvta.to.shared.u64 t, %1; cvt.u32.u64 %0, t; }"
        : "=r"(a) : "l"(p));
    return a;
}
static __device__ __forceinline__ uint32_t sw128(uint32_t off) {
    return off ^ ((off >> 3) & 0x70);
}
__device__ __forceinline__ unsigned pack_hi_(float x, float y) {
    return (unsigned)__bfloat16_as_ushort(__float2bfloat16(x))
         | ((unsigned)__bfloat16_as_ushort(__float2bfloat16(y)) << 16);
}
__device__ __forceinline__ unsigned pack_lo_(float x, float y) {
    float rx = x - __bfloat162float(__float2bfloat16(x));
    float ry = y - __bfloat162float(__float2bfloat16(y));
    return pack_hi_(rx, ry);
}

// cp.async (sm_80+; base-target safe)
__device__ __forceinline__ void cp16_(void* smem_dst, const void* gsrc) {
    uint32_t d = smem_u32_(smem_dst);
    asm volatile("cp.async.cg.shared.global [%0], [%1], 16;" :: "r"(d), "l"(gsrc));
}
#define CP_COMMIT() asm volatile("cp.async.commit_group;" ::: "memory")
#define CP_WAIT1()  asm volatile("cp.async.wait_group 1;" ::: "memory")
#define CP_WAIT0()  asm volatile("cp.async.wait_group 0;" ::: "memory")

// ldmatrix x4 (sm_75+)
#define LDMATRIX_X4(r0, r1, r2, r3, addr) \
    asm volatile("ldmatrix.sync.aligned.m8n8.x4.shared.b16 {%0,%1,%2,%3}, [%4];" \
                 : "=r"(r0), "=r"(r1), "=r"(r2), "=r"(r3) : "r"(addr))

// mma m16n8k16 bf16 (sm_80+)
#define MMA_BF16(d, a, b0v, b1v) \
    asm volatile("mma.sync.aligned.m16n8k16.row.col.f32.bf16.bf16.f32 " \
                 "{%0,%1,%2,%3}, {%4,%5,%6,%7}, {%8,%9}, {%0,%1,%2,%3};" \
                 : "+f"((d)[0]), "+f"((d)[1]), "+f"((d)[2]), "+f"((d)[3]) \
                 : "r"((a)[0]), "r"((a)[1]), "r"((a)[2]), "r"((a)[3]), \
                   "r"(b0v), "r"(b1v))

// ---------------- bf16 split conversion (x, Wih only) ----------------
__global__ __launch_bounds__(256) void split_bf16_kernel(
    const float* __restrict__ src, int to_w, size_t n4)
{
    size_t i = (size_t)blockIdx.x * blockDim.x + threadIdx.x;
    if (i >= n4) return;
    const float4* s = (const float4*)src;
    __nv_bfloat162* dh = (__nv_bfloat162*)(to_w ? g_w_hi : g_a_hi);
    __nv_bfloat162* dl = (__nv_bfloat162*)(to_w ? g_w_lo : g_a_lo);
    float4 v = s[i];
    __nv_bfloat16 h0 = __float2bfloat16(v.x);
    __nv_bfloat16 h1 = __float2bfloat16(v.y);
    __nv_bfloat16 h2 = __float2bfloat16(v.z);
    __nv_bfloat16 h3 = __float2bfloat16(v.w);
    __nv_bfloat16 l0 = __float2bfloat16(v.x - __bfloat162float(h0));
    __nv_bfloat16 l1 = __float2bfloat16(v.y - __bfloat162float(h1));
    __nv_bfloat16 l2 = __float2bfloat16(v.z - __bfloat162float(h2));
    __nv_bfloat16 l3 = __float2bfloat16(v.w - __bfloat162float(h3));
    dh[i * 2 + 0] = __halves2bfloat162(h0, h1);
    dh[i * 2 + 1] = __halves2bfloat162(h2, h3);
    dl[i * 2 + 0] = __halves2bfloat162(l0, l1);
    dl[i * 2 + 1] = __halves2bfloat162(l2, l3);
}

// ---------------- HMMA projection (unchanged from passing R8) ----------------
#define PSTG 16384
#define PROJ_SMEM_TOTAL (4 * PSTG + 512)

__global__ __launch_bounds__(256) void proj_mma_kernel(
    const float* __restrict__ b1, const float* __restrict__ b2, int K)
{
    extern __shared__ char smem[];
    float* bias_s = (float*)(smem + 4 * PSTG);

    const int tid  = threadIdx.x;
    const int lane = tid & 31;
    const int w    = tid >> 5;
    const int wm   = w & 3;
    const int wn   = w >> 2;
    const int n0   = blockIdx.x * 128;
    const int m0   = blockIdx.y * 128;

    if (tid < 128) bias_s[tid] = b1[n0 + tid] + b2[n0 + tid];

    const int kchunks = K >> 6;
    const int C = 3 * kchunks;

    auto prefetch = [&](int c, int stage) {
        const int s  = c / kchunks;
        const int kc = c % kchunks;
        const __nv_bfloat16* a_src = (s == 2) ? g_a_lo : g_a_hi;
        const __nv_bfloat16* w_src = (s == 1) ? g_w_lo : g_w_hi;
        char* abuf = smem + stage * 2 * PSTG;
        char* bbuf = abuf + PSTG;
#pragma unroll
        for (int i = 0; i < 4; i++) {
            int id  = tid + i * 256;
            int row = id >> 3;
            int ch  = id & 7;
            cp16_(abuf + sw128((uint32_t)(row * 128 + ch * 16)),
                  a_src + (size_t)(m0 + row) * K + kc * 64 + ch * 8);
            cp16_(bbuf + sw128((uint32_t)(row * 128 + ch * 16)),
                  w_src + (size_t)(n0 + row) * K + kc * 64 + ch * 8);
        }
    };

    float acc[2][8][4];
#pragma unroll
    for (int mf = 0; mf < 2; mf++)
#pragma unroll
        for (int nf = 0; nf < 8; nf++)
#pragma unroll
            for (int q = 0; q < 4; q++) acc[mf][nf][q] = 0.0f;

    prefetch(0, 0);
    CP_COMMIT();

    const int lrow = lane & 15;
    const int lch  = (lane >> 4) * 16;

    for (int c = 0; c < C; c++) {
        if (c + 1 < C) { prefetch(c + 1, (c + 1) & 1); CP_COMMIT(); CP_WAIT1(); }
        else           { CP_WAIT0(); }
        __syncthreads();

        char* abuf = smem + (c & 1) * 2 * PSTG;
        char* bbuf = abuf + PSTG;
        const uint32_t abase = smem_u32_(abuf);
        const uint32_t bbase = smem_u32_(bbuf);

#pragma unroll
        for (int k16 = 0; k16 < 4; k16++) {
            uint32_t afr[2][4];
#pragma unroll
            for (int mf = 0; mf < 2; mf++) {
                uint32_t addr = abase +
                    sw128((uint32_t)((wm * 32 + mf * 16 + lrow) * 128 + k16 * 32 + lch));
                LDMATRIX_X4(afr[mf][0], afr[mf][1], afr[mf][2], afr[mf][3], addr);
            }
#pragma unroll
            for (int nf2 = 0; nf2 < 4; nf2++) {
                uint32_t bm0, bm1, bm2, bm3;
                uint32_t addr = bbase +
                    sw128((uint32_t)((wn * 64 + nf2 * 16 + lrow) * 128 + k16 * 32 + lch));
                LDMATRIX_X4(bm0, bm1, bm2, bm3, addr);
#pragma unroll
                for (int mf = 0; mf < 2; mf++) {
                    MMA_BF16(acc[mf][2 * nf2 + 0], afr[mf], bm0, bm2);
                    MMA_BF16(acc[mf][2 * nf2 + 1], afr[mf], bm1, bm3);
                }
            }
        }
        __syncthreads();
    }

    const int rrow = lane >> 2;
    const int cq   = (lane & 3) * 2;
#pragma unroll
    for (int mf = 0; mf < 2; mf++) {
#pragma unroll
        for (int rr = 0; rr < 2; rr++) {
            int m = m0 + wm * 32 + mf * 16 + rrow + rr * 8;
            int t = m & (TT - 1);
            int b = m >> 9;
            float* obase = g_xp + ((size_t)t * BB + b) * G4;
#pragma unroll
            for (int nf = 0; nf < 8; nf++) {
                int nl = wn * 64 + nf * 8 + cq;
                int n  = n0 + nl;
                int g  = n >> 8;
                int jj = n & 255;
                float bv0 = bias_s[nl], bv1 = bias_s[nl + 1];
                float2 v = { acc[mf][nf][2 * rr + 0] + bv0,
                             acc[mf][nf][2 * rr + 1] + bv1 };
                *(float2*)(obase + (jj >> 1) * 8 + g * 2) = v;
            }
        }
    }
}

// ---------------- persistent LSTM layer kernel ----------------
// R8 topology: grid (8, 16); CTA = 32 batches x 16 j x 4 gates; warp = n16 x k-half.
// R10 deltas: producer-pre-split h (cp.async stage), stamp barrier.
#define WPLANE 36864                    // 64 rows x 576B
#define HPLANE 18432                    // 32 rows x 576B
#define GBOFF  (2 * WPLANE + 2 * HPLANE)        // 110592
#define PERSIST_SMEM_BYTES (GBOFF + 2 * 32 * 64 * 4)  // 126976

__global__ __launch_bounds__(256, 1) void lstm_persist_kernel(
    const float* __restrict__ Whh, int write_a)
{
    extern __shared__ char smem[];
    char* w_hi = smem;
    char* w_lo = smem + WPLANE;
    char* h_hi = smem + 2 * WPLANE;
    char* h_lo = smem + 2 * WPLANE + HPLANE;
    float* gb  = (float*)(smem + GBOFF);     // [khalf][32][64]

    const int tid  = threadIdx.x;
    const int lane = tid & 31;
    const int wid  = tid >> 5;
    const int ns   = wid & 3;        // gate slice (n16)
    const int kh   = wid >> 2;       // k half
    const int jg   = tid & 7;        // j pair (elementwise role)
    const int bl   = tid >> 3;       // local batch (elementwise role)
    const int grp  = blockIdx.x;
    const int jy   = blockIdx.y;
    const int b0   = grp * 32;
    const int j0   = jy * 16;
    const int b    = b0 + bl;
    const int j    = j0 + 2 * jg;
    const int jp   = j >> 1;

    // ---- load + split Whh slice into swizzled SMEM bf16 planes
    for (int i = tid; i < 64 * 64; i += 256) {
        int row = i >> 6, kq = i & 63;
        int g = row >> 4, jl = row & 15;
        float4 v = *(const float4*)(Whh + (size_t)(g * HH + j0 + jl) * HH + kq * 4);
        uint2 hi = { pack_hi_(v.x, v.y), pack_hi_(v.z, v.w) };
        uint2 lo = { pack_lo_(v.x, v.y), pack_lo_(v.z, v.w) };
        uint32_t off = sw128((uint32_t)(row * 576 + kq * 8));
        *(uint2*)(w_hi + off) = hi;
        *(uint2*)(w_lo + off) = lo;
    }
    __syncthreads();

    const uint32_t whi_b = smem_u32_(w_hi);
    const uint32_t wlo_b = smem_u32_(w_lo);
    const uint32_t hhi_b = smem_u32_(h_hi);
    const uint32_t hlo_b = smem_u32_(h_lo);
    const int lrow = lane & 15;
    const int lch  = (lane >> 4) * 16;

    // launch-local stamp base (own slot; uniform across group at launch)
    const unsigned base = *(volatile unsigned*)&g_stamp[grp * 32 + jy];

    float c0 = 0.0f, c1 = 0.0f;

    for (int t = 0; t < TT; t++) {
        const int par = t & 1;

        // xp loads first (coalesced, time-major) -> DRAM latency hides under step
        const float* xp = g_xp + ((size_t)t * BB + b) * G4 + (size_t)jp * 8;
        float4 xv0 = *(const float4*)(xp);
        float4 xv1 = *(const float4*)(xp + 4);

        if (t > 0) {
            // ---- stamp poll: threads s<16 spin on group slots until >= base+t
            if (tid < 16) {
                const volatile unsigned* st = &g_stamp[grp * 32 + tid];
                unsigned need = base + (unsigned)t;
                while ((int)(*st - need) < 0) { }
            }
            __syncthreads();

            // ---- stage pre-split h planes via cp.async (32 KB)
            const __nv_bfloat16* shi = g_hsp_hi[par];
            const __nv_bfloat16* slo = g_hsp_lo[par];
            for (int i = tid; i < 2048; i += 256) {
                int pl  = i >> 10;
                int rem = i & 1023;
                int row = rem >> 5;
                int kq  = rem & 31;
                const __nv_bfloat16* src =
                    (pl ? slo : shi) + (size_t)(b0 + row) * HH + kq * 8;
                char* dst = (pl ? h_lo : h_hi) + sw128((uint32_t)(row * 576 + kq * 16));
                cp16_(dst, src);
            }
            CP_COMMIT();
            CP_WAIT0();
            __syncthreads();

            // ---- HMMA: warp = (gate n16 ns) x (k half kh); 3 Dekker terms
            float acc[2][2][4];
#pragma unroll
            for (int mf = 0; mf < 2; mf++)
#pragma unroll
                for (int nf = 0; nf < 2; nf++)
#pragma unroll
                    for (int q = 0; q < 4; q++) acc[mf][nf][q] = 0.0f;

#pragma unroll
            for (int k16 = 0; k16 < 8; k16++) {
                const uint32_t kb = (uint32_t)(kh * 256 + k16 * 32 + lch);
                uint32_t ahi[2][4], alo[2][4];
#pragma unroll
                for (int mf = 0; mf < 2; mf++) {
                    uint32_t roff = sw128((uint32_t)((mf * 16 + lrow) * 576) + kb);
                    LDMATRIX_X4(ahi[mf][0], ahi[mf][1], ahi[mf][2], ahi[mf][3],
                                hhi_b + roff);
                    LDMATRIX_X4(alo[mf][0], alo[mf][1], alo[mf][2], alo[mf][3],
                                hlo_b + roff);
                }
                uint32_t woff = sw128((uint32_t)((ns * 16 + lrow) * 576) + kb);
                uint32_t bh0, bh1, bh2, bh3, bl0, bl1, bl2, bl3;
                LDMATRIX_X4(bh0, bh1, bh2, bh3, whi_b + woff);
                LDMATRIX_X4(bl0, bl1, bl2, bl3, wlo_b + woff);
#pragma unroll
                for (int mf = 0; mf < 2; mf++) {
                    MMA_BF16(acc[mf][0], ahi[mf], bh0, bh2);
                    MMA_BF16(acc[mf][1], ahi[mf], bh1, bh3);
                    MMA_BF16(acc[mf][0], ahi[mf], bl0, bl2);
                    MMA_BF16(acc[mf][1], ahi[mf], bl1, bl3);
                    MMA_BF16(acc[mf][0], alo[mf], bh0, bh2);
                    MMA_BF16(acc[mf][1], alo[mf], bh1, bh3);
                }
            }

            // ---- dump gate partials to SMEM: gb[kh][row][col]
            {
                const int rrow = lane >> 2;
                const int cq   = (lane & 3) * 2;
                float* gbh = gb + kh * (32 * 64);
#pragma unroll
                for (int mf = 0; mf < 2; mf++) {
#pragma unroll
                    for (int nf = 0; nf < 2; nf++) {
                        int col = ns * 16 + nf * 8 + cq;
                        *(float2*)(gbh + (mf * 16 + rrow) * 64 + col) =
                            make_float2(acc[mf][nf][0], acc[mf][nf][1]);
                        *(float2*)(gbh + (mf * 16 + rrow + 8) * 64 + col) =
                            make_float2(acc[mf][nf][2], acc[mf][nf][3]);
                    }
                }
            }
            __syncthreads();
        }

        // ---- elementwise update: thread owns (b, j..j+1), all 4 gates
        float xg[4][2] = { {xv0.x, xv0.y}, {xv0.z, xv0.w},
                           {xv1.x, xv1.y}, {xv1.z, xv1.w} };
        float2 gate[4];
#pragma unroll
        for (int g = 0; g < 4; g++) {
            float gx = 0.0f, gy = 0.0f;
            if (t > 0) {
                int col = g * 16 + 2 * jg;
                float2 p0 = *(float2*)(gb + bl * 64 + col);
                float2 p1 = *(float2*)(gb + 32 * 64 + bl * 64 + col);
                gx = p0.x + p1.x;
                gy = p0.y + p1.y;
            }
            gate[g].x = gx + xg[g][0];
            gate[g].y = gy + xg[g][1];
        }
        float i0 = sigmoidf_(gate[0].x), i1 = sigmoidf_(gate[0].y);
        float f0 = sigmoidf_(gate[1].x), f1 = sigmoidf_(gate[1].y);
        float g0 = tanhf_   (gate[2].x), g1 = tanhf_   (gate[2].y);
        float o0 = sigmoidf_(gate[3].x), o1 = sigmoidf_(gate[3].y);
        c0 = f0 * c0 + i0 * g0;
        c1 = f1 * c1 + i1 * g1;
        float2 hv2;
        hv2.x = o0 * tanhf_(c0);
        hv2.y = o1 * tanhf_(c1);
        __stcg((float2*)(g_h[par ^ 1] + (size_t)b * HH + j), hv2);
        unsigned uhi = pack_hi_(hv2.x, hv2.y);
        unsigned ulo = pack_lo_(hv2.x, hv2.y);
        __stcg((unsigned*)(g_hsp_hi[par ^ 1] + (size_t)b * HH + j), uhi);
        __stcg((unsigned*)(g_hsp_lo[par ^ 1] + (size_t)b * HH + j), ulo);
        if (write_a) {
            *(unsigned*)(g_a_hi + ((size_t)b * TT + t) * HH + j) = uhi;
            *(unsigned*)(g_a_lo + ((size_t)b * TT + t) * HH + j) = ulo;
        }

        // ---- publish stamp (h writes globally visible first)
        __threadfence();
        __syncthreads();
        if (tid == 0)
            *(volatile unsigned*)&g_stamp[grp * 32 + jy] = base + (unsigned)t + 1u;
    }
}

// ---------------- final classifier ----------------
__global__ __launch_bounds__(256) void fc_kernel(
    const float* __restrict__ fcW, const float* __restrict__ fcb,
    float* __restrict__ out)
{
    __shared__ float hrow[HH];
    const int b = blockIdx.x;
    const float* __restrict__ h = g_h[0];   // t=511 writes buffer 0
    for (int k = threadIdx.x; k < HH; k += 256) hrow[k] = h[b * HH + k];
    __syncthreads();

    for (int c = threadIdx.x; c < CDIM; c += 256) {
        const float* __restrict__ w = fcW + (size_t)c * HH;
        float s = fcb[c];
#pragma unroll
        for (int k = 0; k < HH; k += 4) {
            float4 wv = *(const float4*)(w + k);
            s += hrow[k + 0] * wv.x;
            s += hrow[k + 1] * wv.y;
            s += hrow[k + 2] * wv.z;
            s += hrow[k + 3] * wv.w;
        }
        out[(size_t)b * CDIM + c] = s;
    }
}

// ---------------- launch ----------------
extern "C" void kernel_launch(void* const* d_in, const int* in_sizes, int n_in,
                              void* d_out, int out_size)
{
    const float* x    = (const float*)d_in[0];
    const float* Wih0 = (const float*)d_in[1];
    const float* Whh0 = (const float*)d_in[2];
    const float* bih0 = (const float*)d_in[3];
    const float* bhh0 = (const float*)d_in[4];
    const float* Wih1 = (const float*)d_in[5];
    const float* Whh1 = (const float*)d_in[6];
    const float* bih1 = (const float*)d_in[7];
    const float* bhh1 = (const float*)d_in[8];
    const float* fcW  = (const float*)d_in[9];
    const float* fcb  = (const float*)d_in[10];
    float* out = (float*)d_out;

    cudaFuncSetAttribute(lstm_persist_kernel,
                         cudaFuncAttributeMaxDynamicSharedMemorySize,
                         PERSIST_SMEM_BYTES);
    cudaFuncSetAttribute(proj_mma_kernel,
                         cudaFuncAttributeMaxDynamicSharedMemorySize,
                         PROJ_SMEM_TOTAL);

    const dim3 proj_grid(G4 / 128, (BB * TT) / 128);  // (8, 1024)
    const dim3 pers_grid(8, 16);                      // 128 CTAs (R8 topology)

    // ---- layer 0 ----
    {
        size_t n4x = (size_t)BB * TT * IDIM / 4;
        size_t n4w = (size_t)G4 * IDIM / 4;
        split_bf16_kernel<<<(unsigned)((n4x + 255) / 256), 256>>>(x, 0, n4x);
        split_bf16_kernel<<<(unsigned)((n4w + 255) / 256), 256>>>(Wih0, 1, n4w);
        proj_mma_kernel<<<proj_grid, 256, PROJ_SMEM_TOTAL>>>(bih0, bhh0, IDIM);
        lstm_persist_kernel<<<pers_grid, 256, PERSIST_SMEM_BYTES>>>(Whh0, 1);
    }

    // ---- layer 1 (A split written directly by layer-0 recurrence) ----
    {
        size_t n4w = (size_t)G4 * HH / 4;
        split_bf16_kernel<<<(unsigned)((n4w + 255) / 256), 256>>>(Wih1, 1, n4w);
        proj_mma_kernel<<<proj_grid, 256, PROJ_SMEM_TOTAL>>>(bih1, bhh1, HH);
        lstm_persist_kernel<<<pers_grid, 256, PERSIST_SMEM_BYTES>>>(Whh1, 0);
    }

    // ---- classifier ----
    fc_kernel<<<BB, 256>>>(fcW, fcb, out);
}

// round 11
// speedup vs baseline: 1.4151x; 1.1394x over previous
#include <cuda_runtime.h>
#include <cuda_bf16.h>
#include <math.h>
#include <cstdint>

#define BB   256      // batch
#define TT   512      // time steps
#define IDIM 128      // input dim
#define HH   256      // hidden dim
#define CDIM 1000     // classes
#define G4   (4*HH)   // 1024 gate columns

// ---------------- scratch (static device allocations; no cudaMalloc) ----------------
// g_xp layout: [t][b][jp][g][2]
__device__ float g_xp[(size_t)BB * TT * G4];
__device__ __nv_bfloat16 g_hsp_hi[2][BB * HH]; // split hidden, double buffered
__device__ __nv_bfloat16 g_hsp_lo[2][BB * HH];
__device__ unsigned g_stamp[8 * 32];           // per (group, jslice) step stamps

// bf16 split buffers for tensor-core projections
__device__ __nv_bfloat16 g_a_hi[(size_t)BB * TT * HH];
__device__ __nv_bfloat16 g_a_lo[(size_t)BB * TT * HH];
__device__ __nv_bfloat16 g_w_hi[(size_t)G4 * HH];
__device__ __nv_bfloat16 g_w_lo[(size_t)G4 * HH];

// ---------------- generic helpers ----------------
__device__ __forceinline__ float sigmoidf_(float x) {
    return 1.0f / (1.0f + __expf(-x));
}
__device__ __forceinline__ float tanhf_(float x) {
    float ax = fabsf(x);
    float e  = __expf(-2.0f * ax);
    float r  = (1.0f - e) / (1.0f + e);
    return copysignf(r, x);
}
__device__ __forceinline__ uint32_t smem_u32_(const void* p) {
    uint32_t a;
    asm("{ .reg .u64 t; cvta.to.shared.u64 t, %1; cvt.u32.u64 %0, t; }"
        : "=r"(a) : "l"(p));
    return a;
}
static __device__ __forceinline__ uint32_t sw128(uint32_t off) {
    return off ^ ((off >> 3) & 0x70);
}
__device__ __forceinline__ unsigned pack_hi_(float x, float y) {
    return (unsigned)__bfloat16_as_ushort(__float2bfloat16(x))
         | ((unsigned)__bfloat16_as_ushort(__float2bfloat16(y)) << 16);
}
__device__ __forceinline__ unsigned pack_lo_(float x, float y) {
    float rx = x - __bfloat162float(__float2bfloat16(x));
    float ry = y - __bfloat162float(__float2bfloat16(y));
    return pack_hi_(rx, ry);
}
__device__ __forceinline__ unsigned ld_acq_(const unsigned* p) {
    unsigned v;
    asm volatile("ld.acquire.gpu.global.u32 %0, [%1];" : "=r"(v) : "l"(p));
    return v;
}
__device__ __forceinline__ void st_rel_(unsigned* p, unsigned v) {
    asm volatile("st.release.gpu.global.u32 [%0], %1;" :: "l"(p), "r"(v));
}
#define BAR_SYNC(id, cnt) \
    asm volatile("bar.sync %0, %1;" :: "r"(id), "r"(cnt) : "memory")

// cp.async (sm_80+; base-target safe)
__device__ __forceinline__ void cp16_(void* smem_dst, const void* gsrc) {
    uint32_t d = smem_u32_(smem_dst);
    asm volatile("cp.async.cg.shared.global [%0], [%1], 16;" :: "r"(d), "l"(gsrc));
}
#define CP_COMMIT() asm volatile("cp.async.commit_group;" ::: "memory")
#define CP_WAIT1()  asm volatile("cp.async.wait_group 1;" ::: "memory")
#define CP_WAIT0()  asm volatile("cp.async.wait_group 0;" ::: "memory")

// ldmatrix x4 (sm_75+)
#define LDMATRIX_X4(r0, r1, r2, r3, addr) \
    asm volatile("ldmatrix.sync.aligned.m8n8.x4.shared.b16 {%0,%1,%2,%3}, [%4];" \
                 : "=r"(r0), "=r"(r1), "=r"(r2), "=r"(r3) : "r"(addr))

// mma m16n8k16 bf16 (sm_80+)
#define MMA_BF16(d, a, b0v, b1v) \
    asm volatile("mma.sync.aligned.m16n8k16.row.col.f32.bf16.bf16.f32 " \
                 "{%0,%1,%2,%3}, {%4,%5,%6,%7}, {%8,%9}, {%0,%1,%2,%3};" \
                 : "+f"((d)[0]), "+f"((d)[1]), "+f"((d)[2]), "+f"((d)[3]) \
                 : "r"((a)[0]), "r"((a)[1]), "r"((a)[2]), "r"((a)[3]), \
                   "r"(b0v), "r"(b1v))

// ---------------- bf16 split conversion (x, Wih only) ----------------
__global__ __launch_bounds__(256) void split_bf16_kernel(
    const float* __restrict__ src, int to_w, size_t n4)
{
    size_t i = (size_t)blockIdx.x * blockDim.x + threadIdx.x;
    if (i >= n4) return;
    const float4* s = (const float4*)src;
    __nv_bfloat162* dh = (__nv_bfloat162*)(to_w ? g_w_hi : g_a_hi);
    __nv_bfloat162* dl = (__nv_bfloat162*)(to_w ? g_w_lo : g_a_lo);
    float4 v = s[i];
    __nv_bfloat16 h0 = __float2bfloat16(v.x);
    __nv_bfloat16 h1 = __float2bfloat16(v.y);
    __nv_bfloat16 h2 = __float2bfloat16(v.z);
    __nv_bfloat16 h3 = __float2bfloat16(v.w);
    __nv_bfloat16 l0 = __float2bfloat16(v.x - __bfloat162float(h0));
    __nv_bfloat16 l1 = __float2bfloat16(v.y - __bfloat162float(h1));
    __nv_bfloat16 l2 = __float2bfloat16(v.z - __bfloat162float(h2));
    __nv_bfloat16 l3 = __float2bfloat16(v.w - __bfloat162float(h3));
    dh[i * 2 + 0] = __halves2bfloat162(h0, h1);
    dh[i * 2 + 1] = __halves2bfloat162(h2, h3);
    dl[i * 2 + 0] = __halves2bfloat162(l0, l1);
    dl[i * 2 + 1] = __halves2bfloat162(l2, l3);
}

// ---------------- HMMA projection (unchanged from passing R10) ----------------
#define PSTG 16384
#define PROJ_SMEM_TOTAL (4 * PSTG + 512)

__global__ __launch_bounds__(256) void proj_mma_kernel(
    const float* __restrict__ b1, const float* __restrict__ b2, int K)
{
    extern __shared__ char smem[];
    float* bias_s = (float*)(smem + 4 * PSTG);

    const int tid  = threadIdx.x;
    const int lane = tid & 31;
    const int w    = tid >> 5;
    const int wm   = w & 3;
    const int wn   = w >> 2;
    const int n0   = blockIdx.x * 128;
    const int m0   = blockIdx.y * 128;

    if (tid < 128) bias_s[tid] = b1[n0 + tid] + b2[n0 + tid];

    const int kchunks = K >> 6;
    const int C = 3 * kchunks;

    auto prefetch = [&](int c, int stage) {
        const int s  = c / kchunks;
        const int kc = c % kchunks;
        const __nv_bfloat16* a_src = (s == 2) ? g_a_lo : g_a_hi;
        const __nv_bfloat16* w_src = (s == 1) ? g_w_lo : g_w_hi;
        char* abuf = smem + stage * 2 * PSTG;
        char* bbuf = abuf + PSTG;
#pragma unroll
        for (int i = 0; i < 4; i++) {
            int id  = tid + i * 256;
            int row = id >> 3;
            int ch  = id & 7;
            cp16_(abuf + sw128((uint32_t)(row * 128 + ch * 16)),
                  a_src + (size_t)(m0 + row) * K + kc * 64 + ch * 8);
            cp16_(bbuf + sw128((uint32_t)(row * 128 + ch * 16)),
                  w_src + (size_t)(n0 + row) * K + kc * 64 + ch * 8);
        }
    };

    float acc[2][8][4];
#pragma unroll
    for (int mf = 0; mf < 2; mf++)
#pragma unroll
        for (int nf = 0; nf < 8; nf++)
#pragma unroll
            for (int q = 0; q < 4; q++) acc[mf][nf][q] = 0.0f;

    prefetch(0, 0);
    CP_COMMIT();

    const int lrow = lane & 15;
    const int lch  = (lane >> 4) * 16;

    for (int c = 0; c < C; c++) {
        if (c + 1 < C) { prefetch(c + 1, (c + 1) & 1); CP_COMMIT(); CP_WAIT1(); }
        else           { CP_WAIT0(); }
        __syncthreads();

        char* abuf = smem + (c & 1) * 2 * PSTG;
        char* bbuf = abuf + PSTG;
        const uint32_t abase = smem_u32_(abuf);
        const uint32_t bbase = smem_u32_(bbuf);

#pragma unroll
        for (int k16 = 0; k16 < 4; k16++) {
            uint32_t afr[2][4];
#pragma unroll
            for (int mf = 0; mf < 2; mf++) {
                uint32_t addr = abase +
                    sw128((uint32_t)((wm * 32 + mf * 16 + lrow) * 128 + k16 * 32 + lch));
                LDMATRIX_X4(afr[mf][0], afr[mf][1], afr[mf][2], afr[mf][3], addr);
            }
#pragma unroll
            for (int nf2 = 0; nf2 < 4; nf2++) {
                uint32_t bm0, bm1, bm2, bm3;
                uint32_t addr = bbase +
                    sw128((uint32_t)((wn * 64 + nf2 * 16 + lrow) * 128 + k16 * 32 + lch));
                LDMATRIX_X4(bm0, bm1, bm2, bm3, addr);
#pragma unroll
                for (int mf = 0; mf < 2; mf++) {
                    MMA_BF16(acc[mf][2 * nf2 + 0], afr[mf], bm0, bm2);
                    MMA_BF16(acc[mf][2 * nf2 + 1], afr[mf], bm1, bm3);
                }
            }
        }
        __syncthreads();
    }

    const int rrow = lane >> 2;
    const int cq   = (lane & 3) * 2;
#pragma unroll
    for (int mf = 0; mf < 2; mf++) {
#pragma unroll
        for (int rr = 0; rr < 2; rr++) {
            int m = m0 + wm * 32 + mf * 16 + rrow + rr * 8;
            int t = m & (TT - 1);
            int b = m >> 9;
            float* obase = g_xp + ((size_t)t * BB + b) * G4;
#pragma unroll
            for (int nf = 0; nf < 8; nf++) {
                int nl = wn * 64 + nf * 8 + cq;
                int n  = n0 + nl;
                int g  = n >> 8;
                int jj = n & 255;
                float bv0 = bias_s[nl], bv1 = bias_s[nl + 1];
                float2 v = { acc[mf][nf][2 * rr + 0] + bv0,
                             acc[mf][nf][2 * rr + 1] + bv1 };
                *(float2*)(obase + (jj >> 1) * 8 + g * 2) = v;
            }
        }
    }
}

// ---------------- persistent LSTM layer kernel ----------------
// Grid (8, 16); CTA = 32 batches x 16 j x 4 gates; warp = n16 x k-half.
// R11: split-phase halves (named barriers), release/acquire stamps, no fp32 h.
#define WPLANE 36864                    // 64 rows x 576B
#define HPLANE 18432                    // 32 rows x 576B
#define GBOFF  (2 * WPLANE + 2 * HPLANE)        // 110592
#define PERSIST_SMEM_BYTES (GBOFF + 2 * 32 * 64 * 4)  // 126976

__global__ __launch_bounds__(256, 1) void lstm_persist_kernel(
    const float* __restrict__ Whh, int write_a)
{
    extern __shared__ char smem[];
    char* w_hi = smem;
    char* w_lo = smem + WPLANE;
    char* h_hi = smem + 2 * WPLANE;
    char* h_lo = smem + 2 * WPLANE + HPLANE;
    float* gb  = (float*)(smem + GBOFF);     // [khalf][32][64]

    const int tid  = threadIdx.x;
    const int lane = tid & 31;
    const int wid  = tid >> 5;
    const int ns   = wid & 3;        // gate slice (n16)
    const int kh   = wid >> 2;       // k half == tid>>7
    const int ht   = tid & 127;      // tid within half
    const int jg   = tid & 7;        // j pair (elementwise role)
    const int bl   = tid >> 3;       // local batch (elementwise role)
    const int grp  = blockIdx.x;
    const int jy   = blockIdx.y;
    const int b0   = grp * 32;
    const int j0   = jy * 16;
    const int b    = b0 + bl;
    const int j    = j0 + 2 * jg;
    const int jp   = j >> 1;

    // ---- load + split Whh slice into swizzled SMEM bf16 planes
    for (int i = tid; i < 64 * 64; i += 256) {
        int row = i >> 6, kq = i & 63;
        int g = row >> 4, jl = row & 15;
        float4 v = *(const float4*)(Whh + (size_t)(g * HH + j0 + jl) * HH + kq * 4);
        uint2 hi = { pack_hi_(v.x, v.y), pack_hi_(v.z, v.w) };
        uint2 lo = { pack_lo_(v.x, v.y), pack_lo_(v.z, v.w) };
        uint32_t off = sw128((uint32_t)(row * 576 + kq * 8));
        *(uint2*)(w_hi + off) = hi;
        *(uint2*)(w_lo + off) = lo;
    }
    __syncthreads();

    const uint32_t whi_b = smem_u32_(w_hi);
    const uint32_t wlo_b = smem_u32_(w_lo);
    const uint32_t hhi_b = smem_u32_(h_hi);
    const uint32_t hlo_b = smem_u32_(h_lo);
    const int lrow = lane & 15;
    const int lch  = (lane >> 4) * 16;

    // launch-local stamp base (own slot; uniform across group at launch)
    const unsigned base = *(volatile unsigned*)&g_stamp[grp * 32 + jy];

    float c0 = 0.0f, c1 = 0.0f;

    for (int t = 0; t < TT; t++) {
        const int par = t & 1;

        // xp loads first (coalesced, time-major) -> DRAM latency hides under step
        const float* xp = g_xp + ((size_t)t * BB + b) * G4 + (size_t)jp * 8;
        float4 xv0 = *(const float4*)(xp);
        float4 xv1 = *(const float4*)(xp + 4);

        if (t > 0) {
            // ---- per-half stamp poll: this half needs peer slots kh*8 .. kh*8+7
            if (ht < 8) {
                const unsigned* st = &g_stamp[grp * 32 + kh * 8 + ht];
                unsigned need = base + (unsigned)t;
                while ((int)(ld_acq_(st) - need) < 0) { }
            }
            BAR_SYNC(1 + kh, 128);

            // ---- stage this half's 16KB of pre-split h via cp.async
            const __nv_bfloat16* shi = g_hsp_hi[par];
            const __nv_bfloat16* slo = g_hsp_lo[par];
#pragma unroll
            for (int it = 0; it < 8; it++) {
                int i   = ht + it * 128;          // 0..1023
                int pl  = i >> 9;
                int rem = i & 511;
                int row = rem >> 4;
                int kq  = rem & 15;
                const __nv_bfloat16* src =
                    (pl ? slo : shi) + (size_t)(b0 + row) * HH + kh * 128 + kq * 8;
                char* dst = (pl ? h_lo : h_hi)
                          + sw128((uint32_t)(row * 576 + kh * 256 + kq * 16));
                cp16_(dst, src);
            }
            CP_COMMIT();
            CP_WAIT0();
            BAR_SYNC(1 + kh, 128);

            // ---- HMMA: warp = (gate n16 ns) x (k half kh); 3 Dekker terms
            float acc[2][2][4];
#pragma unroll
            for (int mf = 0; mf < 2; mf++)
#pragma unroll
                for (int nf = 0; nf < 2; nf++)
#pragma unroll
                    for (int q = 0; q < 4; q++) acc[mf][nf][q] = 0.0f;

#pragma unroll
            for (int k16 = 0; k16 < 8; k16++) {
                const uint32_t kb = (uint32_t)(kh * 256 + k16 * 32 + lch);
                uint32_t ahi[2][4], alo[2][4];
#pragma unroll
                for (int mf = 0; mf < 2; mf++) {
                    uint32_t roff = sw128((uint32_t)((mf * 16 + lrow) * 576) + kb);
                    LDMATRIX_X4(ahi[mf][0], ahi[mf][1], ahi[mf][2], ahi[mf][3],
                                hhi_b + roff);
                    LDMATRIX_X4(alo[mf][0], alo[mf][1], alo[mf][2], alo[mf][3],
                                hlo_b + roff);
                }
                uint32_t woff = sw128((uint32_t)((ns * 16 + lrow) * 576) + kb);
                uint32_t bh0, bh1, bh2, bh3, bl0, bl1, bl2, bl3;
                LDMATRIX_X4(bh0, bh1, bh2, bh3, whi_b + woff);
                LDMATRIX_X4(bl0, bl1, bl2, bl3, wlo_b + woff);
#pragma unroll
                for (int mf = 0; mf < 2; mf++) {
                    MMA_BF16(acc[mf][0], ahi[mf], bh0, bh2);
                    MMA_BF16(acc[mf][1], ahi[mf], bh1, bh3);
                    MMA_BF16(acc[mf][0], ahi[mf], bl0, bl2);
                    MMA_BF16(acc[mf][1], ahi[mf], bl1, bl3);
                    MMA_BF16(acc[mf][0], alo[mf], bh0, bh2);
                    MMA_BF16(acc[mf][1], alo[mf], bh1, bh3);
                }
            }

            // ---- dump gate partials to SMEM: gb[kh][row][col]
            {
                const int rrow = lane >> 2;
                const int cq   = (lane & 3) * 2;
                float* gbh = gb + kh * (32 * 64);
#pragma unroll
                for (int mf = 0; mf < 2; mf++) {
#pragma unroll
                    for (int nf = 0; nf < 2; nf++) {
                        int col = ns * 16 + nf * 8 + cq;
                        *(float2*)(gbh + (mf * 16 + rrow) * 64 + col) =
                            make_float2(acc[mf][nf][0], acc[mf][nf][1]);
                        *(float2*)(gbh + (mf * 16 + rrow + 8) * 64 + col) =
                            make_float2(acc[mf][nf][2], acc[mf][nf][3]);
                    }
                }
            }
            __syncthreads();
        }

        // ---- elementwise update: thread owns (b, j..j+1), all 4 gates
        float xg[4][2] = { {xv0.x, xv0.y}, {xv0.z, xv0.w},
                           {xv1.x, xv1.y}, {xv1.z, xv1.w} };
        float2 gate[4];
#pragma unroll
        for (int g = 0; g < 4; g++) {
            float gx = 0.0f, gy = 0.0f;
            if (t > 0) {
                int col = g * 16 + 2 * jg;
                float2 p0 = *(float2*)(gb + bl * 64 + col);
                float2 p1 = *(float2*)(gb + 32 * 64 + bl * 64 + col);
                gx = p0.x + p1.x;
                gy = p0.y + p1.y;
            }
            gate[g].x = gx + xg[g][0];
            gate[g].y = gy + xg[g][1];
        }
        float i0 = sigmoidf_(gate[0].x), i1 = sigmoidf_(gate[0].y);
        float f0 = sigmoidf_(gate[1].x), f1 = sigmoidf_(gate[1].y);
        float g0 = tanhf_   (gate[2].x), g1 = tanhf_   (gate[2].y);
        float o0 = sigmoidf_(gate[3].x), o1 = sigmoidf_(gate[3].y);
        c0 = f0 * c0 + i0 * g0;
        c1 = f1 * c1 + i1 * g1;
        float2 hv2;
        hv2.x = o0 * tanhf_(c0);
        hv2.y = o1 * tanhf_(c1);
        unsigned uhi = pack_hi_(hv2.x, hv2.y);
        unsigned ulo = pack_lo_(hv2.x, hv2.y);
        __stcg((unsigned*)(g_hsp_hi[par ^ 1] + (size_t)b * HH + j), uhi);
        __stcg((unsigned*)(g_hsp_lo[par ^ 1] + (size_t)b * HH + j), ulo);
        if (write_a) {
            *(unsigned*)(g_a_hi + ((size_t)b * TT + t) * HH + j) = uhi;
            *(unsigned*)(g_a_lo + ((size_t)b * TT + t) * HH + j) = ulo;
        }

        // ---- publish stamp: stores -> syncthreads -> tid0 release-store
        __syncthreads();
        if (tid == 0)
            st_rel_(&g_stamp[grp * 32 + jy], base + (unsigned)t + 1u);
    }
}

// ---------------- final classifier (h reconstructed from split planes) ----------------
__global__ __launch_bounds__(256) void fc_kernel(
    const float* __restrict__ fcW, const float* __restrict__ fcb,
    float* __restrict__ out)
{
    __shared__ float hrow[HH];
    const int b = blockIdx.x;
    // final h (t=511, par=1) lands in buffer 0
    if (threadIdx.x < HH) {
        float hi = __bfloat162float(g_hsp_hi[0][b * HH + threadIdx.x]);
        float lo = __bfloat162float(g_hsp_lo[0][b * HH + threadIdx.x]);
        hrow[threadIdx.x] = hi + lo;
    }
    __syncthreads();

    for (int c = threadIdx.x; c < CDIM; c += 256) {
        const float* __restrict__ w = fcW + (size_t)c * HH;
        float s = fcb[c];
#pragma unroll
        for (int k = 0; k < HH; k += 4) {
            float4 wv = *(const float4*)(w + k);
            s += hrow[k + 0] * wv.x;
            s += hrow[k + 1] * wv.y;
            s += hrow[k + 2] * wv.z;
            s += hrow[k + 3] * wv.w;
        }
        out[(size_t)b * CDIM + c] = s;
    }
}

// ---------------- launch ----------------
extern "C" void kernel_launch(void* const* d_in, const int* in_sizes, int n_in,
                              void* d_out, int out_size)
{
    const float* x    = (const float*)d_in[0];
    const float* Wih0 = (const float*)d_in[1];
    const float* Whh0 = (const float*)d_in[2];
    const float* bih0 = (const float*)d_in[3];
    const float* bhh0 = (const float*)d_in[4];
    const float* Wih1 = (const float*)d_in[5];
    const float* Whh1 = (const float*)d_in[6];
    const float* bih1 = (const float*)d_in[7];
    const float* bhh1 = (const float*)d_in[8];
    const float* fcW  = (const float*)d_in[9];
    const float* fcb  = (const float*)d_in[10];
    float* out = (float*)d_out;

    cudaFuncSetAttribute(lstm_persist_kernel,
                         cudaFuncAttributeMaxDynamicSharedMemorySize,
                         PERSIST_SMEM_BYTES);
    cudaFuncSetAttribute(proj_mma_kernel,
                         cudaFuncAttributeMaxDynamicSharedMemorySize,
                         PROJ_SMEM_TOTAL);

    const dim3 proj_grid(G4 / 128, (BB * TT) / 128);  // (8, 1024)
    const dim3 pers_grid(8, 16);                      // 128 CTAs

    // ---- layer 0 ----
    {
        size_t n4x = (size_t)BB * TT * IDIM / 4;
        size_t n4w = (size_t)G4 * IDIM / 4;
        split_bf16_kernel<<<(unsigned)((n4x + 255) / 256), 256>>>(x, 0, n4x);
        split_bf16_kernel<<<(unsigned)((n4w + 255) / 256), 256>>>(Wih0, 1, n4w);
        proj_mma_kernel<<<proj_grid, 256, PROJ_SMEM_TOTAL>>>(bih0, bhh0, IDIM);
        lstm_persist_kernel<<<pers_grid, 256, PERSIST_SMEM_BYTES>>>(Whh0, 1);
    }

    // ---- layer 1 (A split written directly by layer-0 recurrence) ----
    {
        size_t n4w = (size_t)G4 * HH / 4;
        split_bf16_kernel<<<(unsigned)((n4w + 255) / 256), 256>>>(Wih1, 1, n4w);
        proj_mma_kernel<<<proj_grid, 256, PROJ_SMEM_TOTAL>>>(bih1, bhh1, HH);
        lstm_persist_kernel<<<pers_grid, 256, PERSIST_SMEM_BYTES>>>(Whh1, 0);
    }

    // ---- classifier ----
    fc_kernel<<<BB, 256>>>(fcW, fcb, out);
}

// round 13
// speedup vs baseline: 1.4323x; 1.0121x over previous
#include <cuda_runtime.h>
#include <cuda_bf16.h>
#include <math.h>
#include <cstdint>

#define BB   256      // batch
#define TT   512      // time steps
#define IDIM 128      // input dim
#define HH   256      // hidden dim
#define CDIM 1000     // classes
#define G4   (4*HH)   // 1024 gate columns

// ---------------- scratch (static device allocations; no cudaMalloc) ----------------
// g_xp layout: [t][b][jp][g][2]
__device__ float g_xp[(size_t)BB * TT * G4];
__device__ __nv_bfloat16 g_hsp_hi[2][BB * HH]; // split hidden, double buffered
__device__ __nv_bfloat16 g_hsp_lo[2][BB * HH];
__device__ unsigned g_stamp[8 * 32];           // per (group, jslice) step stamps

// bf16 split buffers for tensor-core projections
__device__ __nv_bfloat16 g_a_hi[(size_t)BB * TT * HH];
__device__ __nv_bfloat16 g_a_lo[(size_t)BB * TT * HH];
__device__ __nv_bfloat16 g_w_hi[(size_t)G4 * HH];
__device__ __nv_bfloat16 g_w_lo[(size_t)G4 * HH];

// ---------------- generic helpers ----------------
__device__ __forceinline__ float sigmoidf_(float x) {
    return 1.0f / (1.0f + __expf(-x));
}
__device__ __forceinline__ float tanhf_(float x) {
    float ax = fabsf(x);
    float e  = __expf(-2.0f * ax);
    float r  = (1.0f - e) / (1.0f + e);
    return copysignf(r, x);
}
__device__ __forceinline__ uint32_t smem_u32_(const void* p) {
    uint32_t a;
    asm("{ .reg .u64 t; cvta.to.shared.u64 t, %1; cvt.u32.u64 %0, t; }"
        : "=r"(a) : "l"(p));
    return a;
}
static __device__ __forceinline__ uint32_t sw128(uint32_t off) {
    return off ^ ((off >> 3) & 0x70);
}
__device__ __forceinline__ unsigned pack_hi_(float x, float y) {
    return (unsigned)__bfloat16_as_ushort(__float2bfloat16(x))
         | ((unsigned)__bfloat16_as_ushort(__float2bfloat16(y)) << 16);
}
__device__ __forceinline__ unsigned pack_lo_(float x, float y) {
    float rx = x - __bfloat162float(__float2bfloat16(x));
    float ry = y - __bfloat162float(__float2bfloat16(y));
    return pack_hi_(rx, ry);
}
__device__ __forceinline__ unsigned ld_acq_(const unsigned* p) {
    unsigned v;
    asm volatile("ld.acquire.gpu.global.u32 %0, [%1];" : "=r"(v) : "l"(p));
    return v;
}
__device__ __forceinline__ void st_rel_(unsigned* p, unsigned v) {
    asm volatile("st.release.gpu.global.u32 [%0], %1;" :: "l"(p), "r"(v));
}
#define BAR_SYNC(id, cnt) \
    asm volatile("bar.sync %0, %1;" :: "r"(id), "r"(cnt) : "memory")

// cp.async (sm_80+; base-target safe)
__device__ __forceinline__ void cp16_(void* smem_dst, const void* gsrc) {
    uint32_t d = smem_u32_(smem_dst);
    asm volatile("cp.async.cg.shared.global [%0], [%1], 16;" :: "r"(d), "l"(gsrc));
}
#define CP_COMMIT() asm volatile("cp.async.commit_group;" ::: "memory")
#define CP_WAIT1()  asm volatile("cp.async.wait_group 1;" ::: "memory")
#define CP_WAIT0()  asm volatile("cp.async.wait_group 0;" ::: "memory")

// ldmatrix x4 (sm_75+)
#define LDMATRIX_X4(r0, r1, r2, r3, addr) \
    asm volatile("ldmatrix.sync.aligned.m8n8.x4.shared.b16 {%0,%1,%2,%3}, [%4];" \
                 : "=r"(r0), "=r"(r1), "=r"(r2), "=r"(r3) : "r"(addr))

// mma m16n8k16 bf16 (sm_80+)
#define MMA_BF16(d, a, b0v, b1v) \
    asm volatile("mma.sync.aligned.m16n8k16.row.col.f32.bf16.bf16.f32 " \
                 "{%0,%1,%2,%3}, {%4,%5,%6,%7}, {%8,%9}, {%0,%1,%2,%3};" \
                 : "+f"((d)[0]), "+f"((d)[1]), "+f"((d)[2]), "+f"((d)[3]) \
                 : "r"((a)[0]), "r"((a)[1]), "r"((a)[2]), "r"((a)[3]), \
                   "r"(b0v), "r"(b1v))

// ---------------- bf16 split conversion (x, Wih only) ----------------
__global__ __launch_bounds__(256) void split_bf16_kernel(
    const float* __restrict__ src, int to_w, size_t n4)
{
    size_t i = (size_t)blockIdx.x * blockDim.x + threadIdx.x;
    if (i >= n4) return;
    const float4* s = (const float4*)src;
    __nv_bfloat162* dh = (__nv_bfloat162*)(to_w ? g_w_hi : g_a_hi);
    __nv_bfloat162* dl = (__nv_bfloat162*)(to_w ? g_w_lo : g_a_lo);
    float4 v = s[i];
    __nv_bfloat16 h0 = __float2bfloat16(v.x);
    __nv_bfloat16 h1 = __float2bfloat16(v.y);
    __nv_bfloat16 h2 = __float2bfloat16(v.z);
    __nv_bfloat16 h3 = __float2bfloat16(v.w);
    __nv_bfloat16 l0 = __float2bfloat16(v.x - __bfloat162float(h0));
    __nv_bfloat16 l1 = __float2bfloat16(v.y - __bfloat162float(h1));
    __nv_bfloat16 l2 = __float2bfloat16(v.z - __bfloat162float(h2));
    __nv_bfloat16 l3 = __float2bfloat16(v.w - __bfloat162float(h3));
    dh[i * 2 + 0] = __halves2bfloat162(h0, h1);
    dh[i * 2 + 1] = __halves2bfloat162(h2, h3);
    dl[i * 2 + 0] = __halves2bfloat162(l0, l1);
    dl[i * 2 + 1] = __halves2bfloat162(l2, l3);
}

// ---------------- HMMA projection (unchanged from passing R11) ----------------
#define PSTG 16384
#define PROJ_SMEM_TOTAL (4 * PSTG + 512)

__global__ __launch_bounds__(256) void proj_mma_kernel(
    const float* __restrict__ b1, const float* __restrict__ b2, int K)
{
    extern __shared__ char smem[];
    float* bias_s = (float*)(smem + 4 * PSTG);

    const int tid  = threadIdx.x;
    const int lane = tid & 31;
    const int w    = tid >> 5;
    const int wm   = w & 3;
    const int wn   = w >> 2;
    const int n0   = blockIdx.x * 128;
    const int m0   = blockIdx.y * 128;

    if (tid < 128) bias_s[tid] = b1[n0 + tid] + b2[n0 + tid];

    const int kchunks = K >> 6;
    const int C = 3 * kchunks;

    auto prefetch = [&](int c, int stage) {
        const int s  = c / kchunks;
        const int kc = c % kchunks;
        const __nv_bfloat16* a_src = (s == 2) ? g_a_lo : g_a_hi;
        const __nv_bfloat16* w_src = (s == 1) ? g_w_lo : g_w_hi;
        char* abuf = smem + stage * 2 * PSTG;
        char* bbuf = abuf + PSTG;
#pragma unroll
        for (int i = 0; i < 4; i++) {
            int id  = tid + i * 256;
            int row = id >> 3;
            int ch  = id & 7;
            cp16_(abuf + sw128((uint32_t)(row * 128 + ch * 16)),
                  a_src + (size_t)(m0 + row) * K + kc * 64 + ch * 8);
            cp16_(bbuf + sw128((uint32_t)(row * 128 + ch * 16)),
                  w_src + (size_t)(n0 + row) * K + kc * 64 + ch * 8);
        }
    };

    float acc[2][8][4];
#pragma unroll
    for (int mf = 0; mf < 2; mf++)
#pragma unroll
        for (int nf = 0; nf < 8; nf++)
#pragma unroll
            for (int q = 0; q < 4; q++) acc[mf][nf][q] = 0.0f;

    prefetch(0, 0);
    CP_COMMIT();

    const int lrow = lane & 15;
    const int lch  = (lane >> 4) * 16;

    for (int c = 0; c < C; c++) {
        if (c + 1 < C) { prefetch(c + 1, (c + 1) & 1); CP_COMMIT(); CP_WAIT1(); }
        else           { CP_WAIT0(); }
        __syncthreads();

        char* abuf = smem + (c & 1) * 2 * PSTG;
        char* bbuf = abuf + PSTG;
        const uint32_t abase = smem_u32_(abuf);
        const uint32_t bbase = smem_u32_(bbuf);

#pragma unroll
        for (int k16 = 0; k16 < 4; k16++) {
            uint32_t afr[2][4];
#pragma unroll
            for (int mf = 0; mf < 2; mf++) {
                uint32_t addr = abase +
                    sw128((uint32_t)((wm * 32 + mf * 16 + lrow) * 128 + k16 * 32 + lch));
                LDMATRIX_X4(afr[mf][0], afr[mf][1], afr[mf][2], afr[mf][3], addr);
            }
#pragma unroll
            for (int nf2 = 0; nf2 < 4; nf2++) {
                uint32_t bm0, bm1, bm2, bm3;
                uint32_t addr = bbase +
                    sw128((uint32_t)((wn * 64 + nf2 * 16 + lrow) * 128 + k16 * 32 + lch));
                LDMATRIX_X4(bm0, bm1, bm2, bm3, addr);
#pragma unroll
                for (int mf = 0; mf < 2; mf++) {
                    MMA_BF16(acc[mf][2 * nf2 + 0], afr[mf], bm0, bm2);
                    MMA_BF16(acc[mf][2 * nf2 + 1], afr[mf], bm1, bm3);
                }
            }
        }
        __syncthreads();
    }

    const int rrow = lane >> 2;
    const int cq   = (lane & 3) * 2;
#pragma unroll
    for (int mf = 0; mf < 2; mf++) {
#pragma unroll
        for (int rr = 0; rr < 2; rr++) {
            int m = m0 + wm * 32 + mf * 16 + rrow + rr * 8;
            int t = m & (TT - 1);
            int b = m >> 9;
            float* obase = g_xp + ((size_t)t * BB + b) * G4;
#pragma unroll
            for (int nf = 0; nf < 8; nf++) {
                int nl = wn * 64 + nf * 8 + cq;
                int n  = n0 + nl;
                int g  = n >> 8;
                int jj = n & 255;
                float bv0 = bias_s[nl], bv1 = bias_s[nl + 1];
                float2 v = { acc[mf][nf][2 * rr + 0] + bv0,
                             acc[mf][nf][2 * rr + 1] + bv1 };
                *(float2*)(obase + (jj >> 1) * 8 + g * 2) = v;
            }
        }
    }
}

// ---------------- persistent LSTM layer kernel ----------------
// Grid (8, 16); CTA = 32 batches x 16 j x 4 gates; warp = n16 x k-half.
// Gate-interleaved W rows (r = jl*4 + g): elementwise cell (b, j-pair) depends
// only on warp-pair {ns, ns+4}, so a pairwise bar.sync(1+ns, 64) replaces the
// full-CTA join. g_a stores sit after the stamp release (off the peer chain).
#define WPLANE 36864                    // 64 rows x 576B
#define HPLANE 18432                    // 32 rows x 576B
#define GBOFF  (2 * WPLANE + 2 * HPLANE)        // 110592
#define GBSTRIDE 68                     // floats per gb row (bank stagger)
#define PERSIST_SMEM_BYTES (GBOFF + 2 * 32 * GBSTRIDE * 4)  // 128000

__global__ __launch_bounds__(256, 1) void lstm_persist_kernel(
    const float* __restrict__ Whh, int write_a)
{
    extern __shared__ char smem[];
    char* w_hi = smem;
    char* w_lo = smem + WPLANE;
    char* h_hi = smem + 2 * WPLANE;
    char* h_lo = smem + 2 * WPLANE + HPLANE;
    float* gb  = (float*)(smem + GBOFF);     // [khalf][32][GBSTRIDE]

    const int tid  = threadIdx.x;
    const int lane = tid & 31;
    const int wid  = tid >> 5;
    const int ns   = wid & 3;        // column slice (n16): j range [ns*4, ns*4+4)
    const int kh   = wid >> 2;       // k half == tid>>7
    const int ht   = tid & 127;      // tid within half
    const int grp  = blockIdx.x;
    const int jy   = blockIdx.y;
    const int b0   = grp * 32;
    const int j0   = jy * 16;

    // elementwise ownership: pair-local cell (1 batch x 1 j-pair)
    const int pl   = lane + kh * 32;         // 0..63 within pair
    const int blx  = pl >> 1;                // local batch 0..31
    const int jpl  = pl & 1;                 // j-pair within slice
    const int jl0  = ns * 4 + jpl * 2;       // local j (even of pair)
    const int bx   = b0 + blx;
    const int jx   = j0 + jl0;
    const int jpg  = jx >> 1;                // global j-pair index
    const int cb   = jl0 * 4;                // gb column base (4 gates x 2 j)

    // ---- load + split Whh slice; SMEM row r = jl*4 + g  <->  Whh[g*HH + j0 + jl]
    for (int i = tid; i < 64 * 64; i += 256) {
        int row = i >> 6, kq = i & 63;
        int g = row & 3, jl = row >> 2;
        float4 v = *(const float4*)(Whh + (size_t)(g * HH + j0 + jl) * HH + kq * 4);
        uint2 hi = { pack_hi_(v.x, v.y), pack_hi_(v.z, v.w) };
        uint2 lo = { pack_lo_(v.x, v.y), pack_lo_(v.z, v.w) };
        uint32_t off = sw128((uint32_t)(row * 576 + kq * 8));
        *(uint2*)(w_hi + off) = hi;
        *(uint2*)(w_lo + off) = lo;
    }
    __syncthreads();

    const uint32_t whi_b = smem_u32_(w_hi);
    const uint32_t wlo_b = smem_u32_(w_lo);
    const uint32_t hhi_b = smem_u32_(h_hi);
    const uint32_t hlo_b = smem_u32_(h_lo);
    const int lrow = lane & 15;
    const int lch  = (lane >> 4) * 16;

    // launch-local stamp base (own slot; uniform across group at launch)
    const unsigned base = *(volatile unsigned*)&g_stamp[grp * 32 + jy];

    float c0 = 0.0f, c1 = 0.0f;

    for (int t = 0; t < TT; t++) {
        const int par = t & 1;

        // xp loads first (coalesced, time-major) -> DRAM latency hides under step
        const float* xp = g_xp + ((size_t)t * BB + bx) * G4 + (size_t)jpg * 8;
        float4 xv0 = *(const float4*)(xp);      // g0(j,j+1), g1(j,j+1)
        float4 xv1 = *(const float4*)(xp + 4);  // g2(j,j+1), g3(j,j+1)

        if (t > 0) {
            // ---- per-half stamp poll: this half needs peer slots kh*8 .. kh*8+7
            if (ht < 8) {
                const unsigned* st = &g_stamp[grp * 32 + kh * 8 + ht];
                unsigned need = base + (unsigned)t;
                while ((int)(ld_acq_(st) - need) < 0) { }
            }
            BAR_SYNC(5 + kh, 128);

            // ---- stage this half's 16KB of pre-split h via cp.async
            const __nv_bfloat16* shi = g_hsp_hi[par];
            const __nv_bfloat16* slo = g_hsp_lo[par];
#pragma unroll
            for (int it = 0; it < 8; it++) {
                int i   = ht + it * 128;          // 0..1023
                int pli = i >> 9;
                int rem = i & 511;
                int row = rem >> 4;
                int kq  = rem & 15;
                const __nv_bfloat16* src =
                    (pli ? slo : shi) + (size_t)(b0 + row) * HH + kh * 128 + kq * 8;
                char* dst = (pli ? h_lo : h_hi)
                          + sw128((uint32_t)(row * 576 + kh * 256 + kq * 16));
                cp16_(dst, src);
            }
            CP_COMMIT();
            CP_WAIT0();
            BAR_SYNC(5 + kh, 128);

            // ---- HMMA: warp = (col slice ns) x (k half kh); 3 Dekker terms
            float acc[2][2][4];
#pragma unroll
            for (int mf = 0; mf < 2; mf++)
#pragma unroll
                for (int nf = 0; nf < 2; nf++)
#pragma unroll
                    for (int q = 0; q < 4; q++) acc[mf][nf][q] = 0.0f;

#pragma unroll
            for (int k16 = 0; k16 < 8; k16++) {
                const uint32_t kb = (uint32_t)(kh * 256 + k16 * 32 + lch);
                uint32_t ahi[2][4], alo[2][4];
#pragma unroll
                for (int mf = 0; mf < 2; mf++) {
                    uint32_t roff = sw128((uint32_t)((mf * 16 + lrow) * 576) + kb);
                    LDMATRIX_X4(ahi[mf][0], ahi[mf][1], ahi[mf][2], ahi[mf][3],
                                hhi_b + roff);
                    LDMATRIX_X4(alo[mf][0], alo[mf][1], alo[mf][2], alo[mf][3],
                                hlo_b + roff);
                }
                uint32_t woff = sw128((uint32_t)((ns * 16 + lrow) * 576) + kb);
                uint32_t bh0, bh1, bh2, bh3, bl0, bl1, bl2, bl3;
                LDMATRIX_X4(bh0, bh1, bh2, bh3, whi_b + woff);
                LDMATRIX_X4(bl0, bl1, bl2, bl3, wlo_b + woff);
#pragma unroll
                for (int mf = 0; mf < 2; mf++) {
                    MMA_BF16(acc[mf][0], ahi[mf], bh0, bh2);
                    MMA_BF16(acc[mf][1], ahi[mf], bh1, bh3);
                    MMA_BF16(acc[mf][0], ahi[mf], bl0, bl2);
                    MMA_BF16(acc[mf][1], ahi[mf], bl1, bl3);
                    MMA_BF16(acc[mf][0], alo[mf], bh0, bh2);
                    MMA_BF16(acc[mf][1], alo[mf], bh1, bh3);
                }
            }

            // ---- dump gate partials to SMEM: gb[kh][row][col]
            {
                const int rrow = lane >> 2;
                const int cq   = (lane & 3) * 2;
                float* gbh = gb + kh * (32 * GBSTRIDE);
#pragma unroll
                for (int mf = 0; mf < 2; mf++) {
#pragma unroll
                    for (int nf = 0; nf < 2; nf++) {
                        int col = ns * 16 + nf * 8 + cq;
                        *(float2*)(gbh + (mf * 16 + rrow) * GBSTRIDE + col) =
                            make_float2(acc[mf][nf][0], acc[mf][nf][1]);
                        *(float2*)(gbh + (mf * 16 + rrow + 8) * GBSTRIDE + col) =
                            make_float2(acc[mf][nf][2], acc[mf][nf][3]);
                    }
                }
            }
            // pairwise join: only the two warps of this column slice
            BAR_SYNC(1 + ns, 64);
        }

        // ---- elementwise: thread owns (bx, jx..jx+1), all 4 gates
        float4 q0, q1;   // gates of j even / j odd
        if (t > 0) {
            float4 a0 = *(float4*)(gb + blx * GBSTRIDE + cb);
            float4 a1 = *(float4*)(gb + blx * GBSTRIDE + cb + 4);
            float4 d0 = *(float4*)(gb + 32 * GBSTRIDE + blx * GBSTRIDE + cb);
            float4 d1 = *(float4*)(gb + 32 * GBSTRIDE + blx * GBSTRIDE + cb + 4);
            q0 = make_float4(a0.x + d0.x, a0.y + d0.y, a0.z + d0.z, a0.w + d0.w);
            q1 = make_float4(a1.x + d1.x, a1.y + d1.y, a1.z + d1.z, a1.w + d1.w);
        } else {
            q0 = make_float4(0.f, 0.f, 0.f, 0.f);
            q1 = q0;
        }
        float i0 = sigmoidf_(q0.x + xv0.x), i1 = sigmoidf_(q1.x + xv0.y);
        float f0 = sigmoidf_(q0.y + xv0.z), f1 = sigmoidf_(q1.y + xv0.w);
        float g0 = tanhf_   (q0.z + xv1.x), g1 = tanhf_   (q1.z + xv1.y);
        float o0 = sigmoidf_(q0.w + xv1.z), o1 = sigmoidf_(q1.w + xv1.w);
        c0 = f0 * c0 + i0 * g0;
        c1 = f1 * c1 + i1 * g1;
        float2 hv2;
        hv2.x = o0 * tanhf_(c0);
        hv2.y = o1 * tanhf_(c1);
        unsigned uhi = pack_hi_(hv2.x, hv2.y);
        unsigned ulo = pack_lo_(hv2.x, hv2.y);
        __stcg((unsigned*)(g_hsp_hi[par ^ 1] + (size_t)bx * HH + jx), uhi);
        __stcg((unsigned*)(g_hsp_lo[par ^ 1] + (size_t)bx * HH + jx), ulo);

        // ---- publish stamp: stores -> syncthreads -> tid0 release-store
        __syncthreads();
        if (tid == 0)
            st_rel_(&g_stamp[grp * 32 + jy], base + (unsigned)t + 1u);

        // ---- layer-1 A-operand stores: off the critical chain
        if (write_a) {
            *(unsigned*)(g_a_hi + ((size_t)bx * TT + t) * HH + jx) = uhi;
            *(unsigned*)(g_a_lo + ((size_t)bx * TT + t) * HH + jx) = ulo;
        }
    }
}

// ---------------- final classifier (h reconstructed from split planes) ----------------
__global__ __launch_bounds__(256) void fc_kernel(
    const float* __restrict__ fcW, const float* __restrict__ fcb,
    float* __restrict__ out)
{
    __shared__ float hrow[HH];
    const int b = blockIdx.x;
    // final h (t=511, par=1) lands in buffer 0
    if (threadIdx.x < HH) {
        float hi = __bfloat162float(g_hsp_hi[0][b * HH + threadIdx.x]);
        float lo = __bfloat162float(g_hsp_lo[0][b * HH + threadIdx.x]);
        hrow[threadIdx.x] = hi + lo;
    }
    __syncthreads();

    for (int c = threadIdx.x; c < CDIM; c += 256) {
        const float* __restrict__ w = fcW + (size_t)c * HH;
        float s = fcb[c];
#pragma unroll
        for (int k = 0; k < HH; k += 4) {
            float4 wv = *(const float4*)(w + k);
            s += hrow[k + 0] * wv.x;
            s += hrow[k + 1] * wv.y;
            s += hrow[k + 2] * wv.z;
            s += hrow[k + 3] * wv.w;
        }
        out[(size_t)b * CDIM + c] = s;
    }
}

// ---------------- launch ----------------
extern "C" void kernel_launch(void* const* d_in, const int* in_sizes, int n_in,
                              void* d_out, int out_size)
{
    const float* x    = (const float*)d_in[0];
    const float* Wih0 = (const float*)d_in[1];
    const float* Whh0 = (const float*)d_in[2];
    const float* bih0 = (const float*)d_in[3];
    const float* bhh0 = (const float*)d_in[4];
    const float* Wih1 = (const float*)d_in[5];
    const float* Whh1 = (const float*)d_in[6];
    const float* bih1 = (const float*)d_in[7];
    const float* bhh1 = (const float*)d_in[8];
    const float* fcW  = (const float*)d_in[9];
    const float* fcb  = (const float*)d_in[10];
    float* out = (float*)d_out;

    cudaFuncSetAttribute(lstm_persist_kernel,
                         cudaFuncAttributeMaxDynamicSharedMemorySize,
                         PERSIST_SMEM_BYTES);
    cudaFuncSetAttribute(proj_mma_kernel,
                         cudaFuncAttributeMaxDynamicSharedMemorySize,
                         PROJ_SMEM_TOTAL);

    const dim3 proj_grid(G4 / 128, (BB * TT) / 128);  // (8, 1024)
    const dim3 pers_grid(8, 16);                      // 128 CTAs

    // ---- layer 0 ----
    {
        size_t n4x = (size_t)BB * TT * IDIM / 4;
        size_t n4w = (size_t)G4 * IDIM / 4;
        split_bf16_kernel<<<(unsigned)((n4x + 255) / 256), 256>>>(x, 0, n4x);
        split_bf16_kernel<<<(unsigned)((n4w + 255) / 256), 256>>>(Wih0, 1, n4w);
        proj_mma_kernel<<<proj_grid, 256, PROJ_SMEM_TOTAL>>>(bih0, bhh0, IDIM);
        lstm_persist_kernel<<<pers_grid, 256, PERSIST_SMEM_BYTES>>>(Whh0, 1);
    }

    // ---- layer 1 (A split written directly by layer-0 recurrence) ----
    {
        size_t n4w = (size_t)G4 * HH / 4;
        split_bf16_kernel<<<(unsigned)((n4w + 255) / 256), 256>>>(Wih1, 1, n4w);
        proj_mma_kernel<<<proj_grid, 256, PROJ_SMEM_TOTAL>>>(bih1, bhh1, HH);
        lstm_persist_kernel<<<pers_grid, 256, PERSIST_SMEM_BYTES>>>(Whh1, 0);
    }

    // ---- classifier ----
    fc_kernel<<<BB, 256>>>(fcW, fcb, out);
}

// round 14
// speedup vs baseline: 1.5877x; 1.1085x over previous
#include <cuda_runtime.h>
#include <cuda_bf16.h>
#include <math.h>
#include <cstdint>

#define BB   256      // batch
#define TT   512      // time steps
#define IDIM 128      // input dim
#define HH   256      // hidden dim
#define CDIM 1000     // classes
#define G4   (4*HH)   // 1024 gate columns

// ---------------- scratch (static device allocations; no cudaMalloc) ----------------
// g_xp layout: [t][b][jp][g][2]
__device__ float g_xp[(size_t)BB * TT * G4];
__device__ __nv_bfloat16 g_hsp_hi[2][BB * HH]; // split hidden, double buffered
__device__ __nv_bfloat16 g_hsp_lo[2][BB * HH];
__device__ unsigned g_stamp[8 * 32];           // per (group, jslice) step stamps

// bf16 split buffers for tensor-core projections
__device__ __nv_bfloat16 g_a_hi[(size_t)BB * TT * HH];
__device__ __nv_bfloat16 g_a_lo[(size_t)BB * TT * HH];
__device__ __nv_bfloat16 g_w_hi[(size_t)G4 * HH];
__device__ __nv_bfloat16 g_w_lo[(size_t)G4 * HH];

// ---------------- generic helpers ----------------
__device__ __forceinline__ float sigmoidf_(float x) {
    return 1.0f / (1.0f + __expf(-x));
}
__device__ __forceinline__ float tanhf_(float x) {
    float ax = fabsf(x);
    float e  = __expf(-2.0f * ax);
    float r  = (1.0f - e) / (1.0f + e);
    return copysignf(r, x);
}
__device__ __forceinline__ uint32_t smem_u32_(const void* p) {
    uint32_t a;
    asm("{ .reg .u64 t; cvta.to.shared.u64 t, %1; cvt.u32.u64 %0, t; }"
        : "=r"(a) : "l"(p));
    return a;
}
static __device__ __forceinline__ uint32_t sw128(uint32_t off) {
    return off ^ ((off >> 3) & 0x70);
}
__device__ __forceinline__ unsigned pack_hi_(float x, float y) {
    return (unsigned)__bfloat16_as_ushort(__float2bfloat16(x))
         | ((unsigned)__bfloat16_as_ushort(__float2bfloat16(y)) << 16);
}
__device__ __forceinline__ unsigned pack_lo_(float x, float y) {
    float rx = x - __bfloat162float(__float2bfloat16(x));
    float ry = y - __bfloat162float(__float2bfloat16(y));
    return pack_hi_(rx, ry);
}
__device__ __forceinline__ unsigned ld_acq_(const unsigned* p) {
    unsigned v;
    asm volatile("ld.acquire.gpu.global.u32 %0, [%1];" : "=r"(v) : "l"(p));
    return v;
}
__device__ __forceinline__ void st_rel_(unsigned* p, unsigned v) {
    asm volatile("st.release.gpu.global.u32 [%0], %1;" :: "l"(p), "r"(v));
}
#define BAR_SYNC(id, cnt) \
    asm volatile("bar.sync %0, %1;" :: "r"(id), "r"(cnt) : "memory")

// cp.async (sm_80+; base-target safe)
__device__ __forceinline__ void cp16_(void* smem_dst, const void* gsrc) {
    uint32_t d = smem_u32_(smem_dst);
    asm volatile("cp.async.cg.shared.global [%0], [%1], 16;" :: "r"(d), "l"(gsrc));
}
#define CP_COMMIT() asm volatile("cp.async.commit_group;" ::: "memory")
#define CP_WAIT1()  asm volatile("cp.async.wait_group 1;" ::: "memory")
#define CP_WAIT0()  asm volatile("cp.async.wait_group 0;" ::: "memory")

// ldmatrix x4 (sm_75+)
#define LDMATRIX_X4(r0, r1, r2, r3, addr) \
    asm volatile("ldmatrix.sync.aligned.m8n8.x4.shared.b16 {%0,%1,%2,%3}, [%4];" \
                 : "=r"(r0), "=r"(r1), "=r"(r2), "=r"(r3) : "r"(addr))

// mma m16n8k16 bf16 (sm_80+)
#define MMA_BF16(d, a, b0v, b1v) \
    asm volatile("mma.sync.aligned.m16n8k16.row.col.f32.bf16.bf16.f32 " \
                 "{%0,%1,%2,%3}, {%4,%5,%6,%7}, {%8,%9}, {%0,%1,%2,%3};" \
                 : "+f"((d)[0]), "+f"((d)[1]), "+f"((d)[2]), "+f"((d)[3]) \
                 : "r"((a)[0]), "r"((a)[1]), "r"((a)[2]), "r"((a)[3]), \
                   "r"(b0v), "r"(b1v))

// ---------------- bf16 split conversion (x, Wih only) ----------------
__global__ __launch_bounds__(256) void split_bf16_kernel(
    const float* __restrict__ src, int to_w, size_t n4)
{
    size_t i = (size_t)blockIdx.x * blockDim.x + threadIdx.x;
    if (i >= n4) return;
    const float4* s = (const float4*)src;
    __nv_bfloat162* dh = (__nv_bfloat162*)(to_w ? g_w_hi : g_a_hi);
    __nv_bfloat162* dl = (__nv_bfloat162*)(to_w ? g_w_lo : g_a_lo);
    float4 v = s[i];
    __nv_bfloat16 h0 = __float2bfloat16(v.x);
    __nv_bfloat16 h1 = __float2bfloat16(v.y);
    __nv_bfloat16 h2 = __float2bfloat16(v.z);
    __nv_bfloat16 h3 = __float2bfloat16(v.w);
    __nv_bfloat16 l0 = __float2bfloat16(v.x - __bfloat162float(h0));
    __nv_bfloat16 l1 = __float2bfloat16(v.y - __bfloat162float(h1));
    __nv_bfloat16 l2 = __float2bfloat16(v.z - __bfloat162float(h2));
    __nv_bfloat16 l3 = __float2bfloat16(v.w - __bfloat162float(h3));
    dh[i * 2 + 0] = __halves2bfloat162(h0, h1);
    dh[i * 2 + 1] = __halves2bfloat162(h2, h3);
    dl[i * 2 + 0] = __halves2bfloat162(l0, l1);
    dl[i * 2 + 1] = __halves2bfloat162(l2, l3);
}

// ---------------- HMMA projection (unchanged from passing R13) ----------------
#define PSTG 16384
#define PROJ_SMEM_TOTAL (4 * PSTG + 512)

__global__ __launch_bounds__(256) void proj_mma_kernel(
    const float* __restrict__ b1, const float* __restrict__ b2, int K)
{
    extern __shared__ char smem[];
    float* bias_s = (float*)(smem + 4 * PSTG);

    const int tid  = threadIdx.x;
    const int lane = tid & 31;
    const int w    = tid >> 5;
    const int wm   = w & 3;
    const int wn   = w >> 2;
    const int n0   = blockIdx.x * 128;
    const int m0   = blockIdx.y * 128;

    if (tid < 128) bias_s[tid] = b1[n0 + tid] + b2[n0 + tid];

    const int kchunks = K >> 6;
    const int C = 3 * kchunks;

    auto prefetch = [&](int c, int stage) {
        const int s  = c / kchunks;
        const int kc = c % kchunks;
        const __nv_bfloat16* a_src = (s == 2) ? g_a_lo : g_a_hi;
        const __nv_bfloat16* w_src = (s == 1) ? g_w_lo : g_w_hi;
        char* abuf = smem + stage * 2 * PSTG;
        char* bbuf = abuf + PSTG;
#pragma unroll
        for (int i = 0; i < 4; i++) {
            int id  = tid + i * 256;
            int row = id >> 3;
            int ch  = id & 7;
            cp16_(abuf + sw128((uint32_t)(row * 128 + ch * 16)),
                  a_src + (size_t)(m0 + row) * K + kc * 64 + ch * 8);
            cp16_(bbuf + sw128((uint32_t)(row * 128 + ch * 16)),
                  w_src + (size_t)(n0 + row) * K + kc * 64 + ch * 8);
        }
    };

    float acc[2][8][4];
#pragma unroll
    for (int mf = 0; mf < 2; mf++)
#pragma unroll
        for (int nf = 0; nf < 8; nf++)
#pragma unroll
            for (int q = 0; q < 4; q++) acc[mf][nf][q] = 0.0f;

    prefetch(0, 0);
    CP_COMMIT();

    const int lrow = lane & 15;
    const int lch  = (lane >> 4) * 16;

    for (int c = 0; c < C; c++) {
        if (c + 1 < C) { prefetch(c + 1, (c + 1) & 1); CP_COMMIT(); CP_WAIT1(); }
        else           { CP_WAIT0(); }
        __syncthreads();

        char* abuf = smem + (c & 1) * 2 * PSTG;
        char* bbuf = abuf + PSTG;
        const uint32_t abase = smem_u32_(abuf);
        const uint32_t bbase = smem_u32_(bbuf);

#pragma unroll
        for (int k16 = 0; k16 < 4; k16++) {
            uint32_t afr[2][4];
#pragma unroll
            for (int mf = 0; mf < 2; mf++) {
                uint32_t addr = abase +
                    sw128((uint32_t)((wm * 32 + mf * 16 + lrow) * 128 + k16 * 32 + lch));
                LDMATRIX_X4(afr[mf][0], afr[mf][1], afr[mf][2], afr[mf][3], addr);
            }
#pragma unroll
            for (int nf2 = 0; nf2 < 4; nf2++) {
                uint32_t bm0, bm1, bm2, bm3;
                uint32_t addr = bbase +
                    sw128((uint32_t)((wn * 64 + nf2 * 16 + lrow) * 128 + k16 * 32 + lch));
                LDMATRIX_X4(bm0, bm1, bm2, bm3, addr);
#pragma unroll
                for (int mf = 0; mf < 2; mf++) {
                    MMA_BF16(acc[mf][2 * nf2 + 0], afr[mf], bm0, bm2);
                    MMA_BF16(acc[mf][2 * nf2 + 1], afr[mf], bm1, bm3);
                }
            }
        }
        __syncthreads();
    }

    const int rrow = lane >> 2;
    const int cq   = (lane & 3) * 2;
#pragma unroll
    for (int mf = 0; mf < 2; mf++) {
#pragma unroll
        for (int rr = 0; rr < 2; rr++) {
            int m = m0 + wm * 32 + mf * 16 + rrow + rr * 8;
            int t = m & (TT - 1);
            int b = m >> 9;
            float* obase = g_xp + ((size_t)t * BB + b) * G4;
#pragma unroll
            for (int nf = 0; nf < 8; nf++) {
                int nl = wn * 64 + nf * 8 + cq;
                int n  = n0 + nl;
                int g  = n >> 8;
                int jj = n & 255;
                float bv0 = bias_s[nl], bv1 = bias_s[nl + 1];
                float2 v = { acc[mf][nf][2 * rr + 0] + bv0,
                             acc[mf][nf][2 * rr + 1] + bv1 };
                *(float2*)(obase + (jj >> 1) * 8 + g * 2) = v;
            }
        }
    }
}

// ---------------- persistent LSTM layer kernel ----------------
// Grid (8, 16); CTA = 32 batches x 16 j x 4 gates; warp = n16 x k-half.
// R14: W fragments hoisted into registers (loaded once); h stage split into two
// 8KB commit groups so MMA on k16 0..3 overlaps the in-flight second chunk.
#define WPLANE 36864                    // 64 rows x 576B
#define HPLANE 18432                    // 32 rows x 576B
#define GBOFF  (2 * WPLANE + 2 * HPLANE)        // 110592
#define GBSTRIDE 68                     // floats per gb row (bank stagger)
#define PERSIST_SMEM_BYTES (GBOFF + 2 * 32 * GBSTRIDE * 4)  // 128000

__global__ __launch_bounds__(256, 1) void lstm_persist_kernel(
    const float* __restrict__ Whh, int write_a)
{
    extern __shared__ char smem[];
    char* w_hi = smem;
    char* w_lo = smem + WPLANE;
    char* h_hi = smem + 2 * WPLANE;
    char* h_lo = smem + 2 * WPLANE + HPLANE;
    float* gb  = (float*)(smem + GBOFF);     // [khalf][32][GBSTRIDE]

    const int tid  = threadIdx.x;
    const int lane = tid & 31;
    const int wid  = tid >> 5;
    const int ns   = wid & 3;        // column slice (n16): j range [ns*4, ns*4+4)
    const int kh   = wid >> 2;       // k half == tid>>7
    const int ht   = tid & 127;      // tid within half
    const int grp  = blockIdx.x;
    const int jy   = blockIdx.y;
    const int b0   = grp * 32;
    const int j0   = jy * 16;

    // elementwise ownership: pair-local cell (1 batch x 1 j-pair)
    const int pl   = lane + kh * 32;         // 0..63 within pair
    const int blx  = pl >> 1;                // local batch 0..31
    const int jpl  = pl & 1;                 // j-pair within slice
    const int jl0  = ns * 4 + jpl * 2;       // local j (even of pair)
    const int bx   = b0 + blx;
    const int jx   = j0 + jl0;
    const int jpg  = jx >> 1;                // global j-pair index
    const int cb   = jl0 * 4;                // gb column base (4 gates x 2 j)

    // ---- load + split Whh slice; SMEM row r = jl*4 + g  <->  Whh[g*HH + j0 + jl]
    for (int i = tid; i < 64 * 64; i += 256) {
        int row = i >> 6, kq = i & 63;
        int g = row & 3, jl = row >> 2;
        float4 v = *(const float4*)(Whh + (size_t)(g * HH + j0 + jl) * HH + kq * 4);
        uint2 hi = { pack_hi_(v.x, v.y), pack_hi_(v.z, v.w) };
        uint2 lo = { pack_lo_(v.x, v.y), pack_lo_(v.z, v.w) };
        uint32_t off = sw128((uint32_t)(row * 576 + kq * 8));
        *(uint2*)(w_hi + off) = hi;
        *(uint2*)(w_lo + off) = lo;
    }
    __syncthreads();

    const uint32_t whi_b = smem_u32_(w_hi);
    const uint32_t wlo_b = smem_u32_(w_lo);
    const uint32_t hhi_b = smem_u32_(h_hi);
    const uint32_t hlo_b = smem_u32_(h_lo);
    const int lrow = lane & 15;
    const int lch  = (lane >> 4) * 16;

    // ---- hoist this warp's W fragments into registers (loop-invariant)
    uint32_t wfh[8][4], wfl[8][4];
#pragma unroll
    for (int k16 = 0; k16 < 8; k16++) {
        uint32_t woff = sw128((uint32_t)((ns * 16 + lrow) * 576)
                              + (uint32_t)(kh * 256 + k16 * 32 + lch));
        LDMATRIX_X4(wfh[k16][0], wfh[k16][1], wfh[k16][2], wfh[k16][3], whi_b + woff);
        LDMATRIX_X4(wfl[k16][0], wfl[k16][1], wfl[k16][2], wfl[k16][3], wlo_b + woff);
    }

    // launch-local stamp base (own slot; uniform across group at launch)
    const unsigned base = *(volatile unsigned*)&g_stamp[grp * 32 + jy];

    float c0 = 0.0f, c1 = 0.0f;
    float acc[2][2][4];

    for (int t = 0; t < TT; t++) {
        const int par = t & 1;

        // xp loads first (coalesced, time-major) -> DRAM latency hides under step
        const float* xp = g_xp + ((size_t)t * BB + bx) * G4 + (size_t)jpg * 8;
        float4 xv0 = *(const float4*)(xp);      // g0(j,j+1), g1(j,j+1)
        float4 xv1 = *(const float4*)(xp + 4);  // g2(j,j+1), g3(j,j+1)

        if (t > 0) {
            // ---- per-half stamp poll: this half needs peer slots kh*8 .. kh*8+7
            if (ht < 8) {
                const unsigned* st = &g_stamp[grp * 32 + kh * 8 + ht];
                unsigned need = base + (unsigned)t;
                while ((int)(ld_acq_(st) - need) < 0) { }
            }
            BAR_SYNC(5 + kh, 128);

            // ---- stage this half's h planes in 2 chunks (k16 0..3 | 4..7)
            const __nv_bfloat16* shi = g_hsp_hi[par];
            const __nv_bfloat16* slo = g_hsp_lo[par];
#pragma unroll
            for (int ck = 0; ck < 2; ck++) {
#pragma unroll
                for (int it = 0; it < 4; it++) {
                    int i   = ht + it * 128;          // 0..511
                    int pli = i >> 8;                 // plane
                    int rem = i & 255;
                    int row = rem >> 3;               // 0..31
                    int kq  = (rem & 7) + ck * 8;     // k octet within half
                    const __nv_bfloat16* src =
                        (pli ? slo : shi) + (size_t)(b0 + row) * HH + kh * 128 + kq * 8;
                    char* dst = (pli ? h_lo : h_hi)
                              + sw128((uint32_t)(row * 576 + kh * 256 + kq * 16));
                    cp16_(dst, src);
                }
                CP_COMMIT();
            }

#pragma unroll
            for (int mf = 0; mf < 2; mf++)
#pragma unroll
                for (int nf = 0; nf < 2; nf++)
#pragma unroll
                    for (int q = 0; q < 4; q++) acc[mf][nf][q] = 0.0f;

            // ---- chunk 1 ready -> MMA k16 0..3 while chunk 2 in flight
            CP_WAIT1();
            BAR_SYNC(5 + kh, 128);
#pragma unroll
            for (int k16 = 0; k16 < 4; k16++) {
                const uint32_t kb = (uint32_t)(kh * 256 + k16 * 32 + lch);
                uint32_t ahi[2][4], alo[2][4];
#pragma unroll
                for (int mf = 0; mf < 2; mf++) {
                    uint32_t roff = sw128((uint32_t)((mf * 16 + lrow) * 576) + kb);
                    LDMATRIX_X4(ahi[mf][0], ahi[mf][1], ahi[mf][2], ahi[mf][3],
                                hhi_b + roff);
                    LDMATRIX_X4(alo[mf][0], alo[mf][1], alo[mf][2], alo[mf][3],
                                hlo_b + roff);
                }
#pragma unroll
                for (int mf = 0; mf < 2; mf++) {
                    MMA_BF16(acc[mf][0], ahi[mf], wfh[k16][0], wfh[k16][2]);
                    MMA_BF16(acc[mf][1], ahi[mf], wfh[k16][1], wfh[k16][3]);
                    MMA_BF16(acc[mf][0], ahi[mf], wfl[k16][0], wfl[k16][2]);
                    MMA_BF16(acc[mf][1], ahi[mf], wfl[k16][1], wfl[k16][3]);
                    MMA_BF16(acc[mf][0], alo[mf], wfh[k16][0], wfh[k16][2]);
                    MMA_BF16(acc[mf][1], alo[mf], wfh[k16][1], wfh[k16][3]);
                }
            }

            // ---- chunk 2 ready -> MMA k16 4..7
            CP_WAIT0();
            BAR_SYNC(5 + kh, 128);
#pragma unroll
            for (int k16 = 4; k16 < 8; k16++) {
                const uint32_t kb = (uint32_t)(kh * 256 + k16 * 32 + lch);
                uint32_t ahi[2][4], alo[2][4];
#pragma unroll
                for (int mf = 0; mf < 2; mf++) {
                    uint32_t roff = sw128((uint32_t)((mf * 16 + lrow) * 576) + kb);
                    LDMATRIX_X4(ahi[mf][0], ahi[mf][1], ahi[mf][2], ahi[mf][3],
                                hhi_b + roff);
                    LDMATRIX_X4(alo[mf][0], alo[mf][1], alo[mf][2], alo[mf][3],
                                hlo_b + roff);
                }
#pragma unroll
                for (int mf = 0; mf < 2; mf++) {
                    MMA_BF16(acc[mf][0], ahi[mf], wfh[k16][0], wfh[k16][2]);
                    MMA_BF16(acc[mf][1], ahi[mf], wfh[k16][1], wfh[k16][3]);
                    MMA_BF16(acc[mf][0], ahi[mf], wfl[k16][0], wfl[k16][2]);
                    MMA_BF16(acc[mf][1], ahi[mf], wfl[k16][1], wfl[k16][3]);
                    MMA_BF16(acc[mf][0], alo[mf], wfh[k16][0], wfh[k16][2]);
                    MMA_BF16(acc[mf][1], alo[mf], wfh[k16][1], wfh[k16][3]);
                }
            }

            // ---- dump gate partials to SMEM: gb[kh][row][col]
            {
                const int rrow = lane >> 2;
                const int cq   = (lane & 3) * 2;
                float* gbh = gb + kh * (32 * GBSTRIDE);
#pragma unroll
                for (int mf = 0; mf < 2; mf++) {
#pragma unroll
                    for (int nf = 0; nf < 2; nf++) {
                        int col = ns * 16 + nf * 8 + cq;
                        *(float2*)(gbh + (mf * 16 + rrow) * GBSTRIDE + col) =
                            make_float2(acc[mf][nf][0], acc[mf][nf][1]);
                        *(float2*)(gbh + (mf * 16 + rrow + 8) * GBSTRIDE + col) =
                            make_float2(acc[mf][nf][2], acc[mf][nf][3]);
                    }
                }
            }
            // pairwise join: only the two warps of this column slice
            BAR_SYNC(1 + ns, 64);
        }

        // ---- elementwise: thread owns (bx, jx..jx+1), all 4 gates
        float4 q0, q1;   // gates of j even / j odd
        if (t > 0) {
            float4 a0 = *(float4*)(gb + blx * GBSTRIDE + cb);
            float4 a1 = *(float4*)(gb + blx * GBSTRIDE + cb + 4);
            float4 d0 = *(float4*)(gb + 32 * GBSTRIDE + blx * GBSTRIDE + cb);
            float4 d1 = *(float4*)(gb + 32 * GBSTRIDE + blx * GBSTRIDE + cb + 4);
            q0 = make_float4(a0.x + d0.x, a0.y + d0.y, a0.z + d0.z, a0.w + d0.w);
            q1 = make_float4(a1.x + d1.x, a1.y + d1.y, a1.z + d1.z, a1.w + d1.w);
        } else {
            q0 = make_float4(0.f, 0.f, 0.f, 0.f);
            q1 = q0;
        }
        float i0 = sigmoidf_(q0.x + xv0.x), i1 = sigmoidf_(q1.x + xv0.y);
        float f0 = sigmoidf_(q0.y + xv0.z), f1 = sigmoidf_(q1.y + xv0.w);
        float g0 = tanhf_   (q0.z + xv1.x), g1 = tanhf_   (q1.z + xv1.y);
        float o0 = sigmoidf_(q0.w + xv1.z), o1 = sigmoidf_(q1.w + xv1.w);
        c0 = f0 * c0 + i0 * g0;
        c1 = f1 * c1 + i1 * g1;
        float2 hv2;
        hv2.x = o0 * tanhf_(c0);
        hv2.y = o1 * tanhf_(c1);
        unsigned uhi = pack_hi_(hv2.x, hv2.y);
        unsigned ulo = pack_lo_(hv2.x, hv2.y);
        __stcg((unsigned*)(g_hsp_hi[par ^ 1] + (size_t)bx * HH + jx), uhi);
        __stcg((unsigned*)(g_hsp_lo[par ^ 1] + (size_t)bx * HH + jx), ulo);

        // ---- publish stamp: stores -> syncthreads -> tid0 release-store
        __syncthreads();
        if (tid == 0)
            st_rel_(&g_stamp[grp * 32 + jy], base + (unsigned)t + 1u);

        // ---- layer-1 A-operand stores: off the critical chain
        if (write_a) {
            *(unsigned*)(g_a_hi + ((size_t)bx * TT + t) * HH + jx) = uhi;
            *(unsigned*)(g_a_lo + ((size_t)bx * TT + t) * HH + jx) = ulo;
        }
    }
}

// ---------------- final classifier (h reconstructed from split planes) ----------------
__global__ __launch_bounds__(256) void fc_kernel(
    const float* __restrict__ fcW, const float* __restrict__ fcb,
    float* __restrict__ out)
{
    __shared__ float hrow[HH];
    const int b = blockIdx.x;
    // final h (t=511, par=1) lands in buffer 0
    if (threadIdx.x < HH) {
        float hi = __bfloat162float(g_hsp_hi[0][b * HH + threadIdx.x]);
        float lo = __bfloat162float(g_hsp_lo[0][b * HH + threadIdx.x]);
        hrow[threadIdx.x] = hi + lo;
    }
    __syncthreads();

    for (int c = threadIdx.x; c < CDIM; c += 256) {
        const float* __restrict__ w = fcW + (size_t)c * HH;
        float s = fcb[c];
#pragma unroll
        for (int k = 0; k < HH; k += 4) {
            float4 wv = *(const float4*)(w + k);
            s += hrow[k + 0] * wv.x;
            s += hrow[k + 1] * wv.y;
            s += hrow[k + 2] * wv.z;
            s += hrow[k + 3] * wv.w;
        }
        out[(size_t)b * CDIM + c] = s;
    }
}

// ---------------- launch ----------------
extern "C" void kernel_launch(void* const* d_in, const int* in_sizes, int n_in,
                              void* d_out, int out_size)
{
    const float* x    = (const float*)d_in[0];
    const float* Wih0 = (const float*)d_in[1];
    const float* Whh0 = (const float*)d_in[2];
    const float* bih0 = (const float*)d_in[3];
    const float* bhh0 = (const float*)d_in[4];
    const float* Wih1 = (const float*)d_in[5];
    const float* Whh1 = (const float*)d_in[6];
    const float* bih1 = (const float*)d_in[7];
    const float* bhh1 = (const float*)d_in[8];
    const float* fcW  = (const float*)d_in[9];
    const float* fcb  = (const float*)d_in[10];
    float* out = (float*)d_out;

    cudaFuncSetAttribute(lstm_persist_kernel,
                         cudaFuncAttributeMaxDynamicSharedMemorySize,
                         PERSIST_SMEM_BYTES);
    cudaFuncSetAttribute(proj_mma_kernel,
                         cudaFuncAttributeMaxDynamicSharedMemorySize,
                         PROJ_SMEM_TOTAL);

    const dim3 proj_grid(G4 / 128, (BB * TT) / 128);  // (8, 1024)
    const dim3 pers_grid(8, 16);                      // 128 CTAs

    // ---- layer 0 ----
    {
        size_t n4x = (size_t)BB * TT * IDIM / 4;
        size_t n4w = (size_t)G4 * IDIM / 4;
        split_bf16_kernel<<<(unsigned)((n4x + 255) / 256), 256>>>(x, 0, n4x);
        split_bf16_kernel<<<(unsigned)((n4w + 255) / 256), 256>>>(Wih0, 1, n4w);
        proj_mma_kernel<<<proj_grid, 256, PROJ_SMEM_TOTAL>>>(bih0, bhh0, IDIM);
        lstm_persist_kernel<<<pers_grid, 256, PERSIST_SMEM_BYTES>>>(Whh0, 1);
    }

    // ---- layer 1 (A split written directly by layer-0 recurrence) ----
    {
        size_t n4w = (size_t)G4 * HH / 4;
        split_bf16_kernel<<<(unsigned)((n4w + 255) / 256), 256>>>(Wih1, 1, n4w);
        proj_mma_kernel<<<proj_grid, 256, PROJ_SMEM_TOTAL>>>(bih1, bhh1, HH);
        lstm_persist_kernel<<<pers_grid, 256, PERSIST_SMEM_BYTES>>>(Whh1, 0);
    }

    // ---- classifier ----
    fc_kernel<<<BB, 256>>>(fcW, fcb, out);
}